// round 14
// baseline (speedup 1.0000x reference)
#include <cuda_runtime.h>
#include <cuda_bf16.h>
#include <math.h>
#include <stdint.h>

#define B_ROWS 32768
#define IN_DIM 1024
#define HID    64
#define COMM   256
#define KP     8192
#define MAXC   48

#define ROWB   144                 // dist smem row stride: 128B data (K=64 bf16) + 16B pad
#define TILEB  (128 * ROWB)        // 18432
#define STAGEB (2 * TILEB)         // A tile + B tile per stage = 36864
#define STAGES 4
#define DSMEM  (STAGES * STAGEB)   // 147456 dynamic smem

// ---------- scratch (no runtime allocation allowed) ----------
__device__ float  g_h3[B_ROWS * COMM];
__device__ float  g_sample[B_ROWS * COMM];
__device__ __nv_bfloat16 g_sbf[B_ROWS * COMM];
__device__ __nv_bfloat16 g_pbf[KP * COMM];
__device__ float  g_sq[B_ROWS];
__device__ float  g_pn[KP];
__device__ unsigned int g_pnmax_u;   // monotone: atomicMax is idempotent across replays
__device__ int    g_cnt[B_ROWS];
__device__ int    g_cand[B_ROWS * MAXC];
__device__ int    g_idx[B_ROWS];
__device__ double g_acc[2];

// ---------- proto squared norms + bf16 conversion (+ accumulator zeroing) ----------
__global__ void k_pn(const float* __restrict__ protos) {
    if (blockIdx.x == 0 && threadIdx.x == 0) { g_acc[0] = 0.0; g_acc[1] = 0.0; }
    int row  = blockIdx.x * 8 + (threadIdx.x >> 5);
    int lane = threadIdx.x & 31;
    float a = 0.f;
#pragma unroll
    for (int m = 0; m < 8; m++) {
        float v = protos[row * COMM + lane + 32 * m];
        g_pbf[row * COMM + lane + 32 * m] = __float2bfloat16_rn(v);
        a = fmaf(v, v, a);
    }
#pragma unroll
    for (int o = 16; o > 0; o >>= 1) a += __shfl_down_sync(0xffffffffu, a, o);
    if (lane == 0) {
        g_pn[row] = a;
        atomicMax(&g_pnmax_u, __float_as_uint(a));
    }
}

// ---------- fused MLP (unchanged, validated) ----------
__global__ __launch_bounds__(256) void k_mlp(
    const float* __restrict__ x,  const float* __restrict__ Wf, const float* __restrict__ bf,
    const float* __restrict__ W0, const float* __restrict__ b0,
    const float* __restrict__ W1, const float* __restrict__ b1)
{
    __shared__ float bufA[64 * 68];
    __shared__ float bufB[64 * 68];
    const int t  = threadIdx.x;
    const int tx = t & 15, ty = t >> 4;
    const int rowbase = blockIdx.x * 64;

    float* sX = bufA;
    float* sW = bufA + 32 * 68;

    float acc[4][4];
#pragma unroll
    for (int r = 0; r < 4; r++)
#pragma unroll
        for (int c = 0; c < 4; c++) acc[r][c] = 0.f;

    for (int kc = 0; kc < IN_DIM; kc += 32) {
        {
            int row = t >> 2, kq = (t & 3) * 8;
            const float* src = &x[(rowbase + row) * IN_DIM + kc + kq];
            float4 v0 = *(const float4*)(src);
            float4 v1 = *(const float4*)(src + 4);
            sX[(kq + 0) * 68 + row] = v0.x; sX[(kq + 1) * 68 + row] = v0.y;
            sX[(kq + 2) * 68 + row] = v0.z; sX[(kq + 3) * 68 + row] = v0.w;
            sX[(kq + 4) * 68 + row] = v1.x; sX[(kq + 5) * 68 + row] = v1.y;
            sX[(kq + 6) * 68 + row] = v1.z; sX[(kq + 7) * 68 + row] = v1.w;
            int k = t >> 3, cq = (t & 7) * 8;
            const float* ws = &Wf[(kc + k) * HID + cq];
            float4 w0 = *(const float4*)(ws);
            float4 w1 = *(const float4*)(ws + 4);
            *(float4*)&sW[k * 68 + cq]     = w0;
            *(float4*)&sW[k * 68 + cq + 4] = w1;
        }
        __syncthreads();
#pragma unroll 8
        for (int k = 0; k < 32; k++) {
            float a[4], w[4];
#pragma unroll
            for (int r = 0; r < 4; r++) a[r] = sX[k * 68 + ty + 16 * r];
#pragma unroll
            for (int c = 0; c < 4; c++) w[c] = sW[k * 68 + tx + 16 * c];
#pragma unroll
            for (int r = 0; r < 4; r++)
#pragma unroll
                for (int c = 0; c < 4; c++) acc[r][c] = fmaf(a[r], w[c], acc[r][c]);
        }
        __syncthreads();
    }
#pragma unroll
    for (int r = 0; r < 4; r++)
#pragma unroll
        for (int c = 0; c < 4; c++)
            bufB[(ty + 16 * r) * 68 + tx + 16 * c] = acc[r][c] + bf[tx + 16 * c];

    {
        int k = t >> 2, cq = (t & 3) * 16;
#pragma unroll
        for (int i = 0; i < 4; i++)
            *(float4*)&bufA[k * 68 + cq + 4 * i] = *(const float4*)&W0[k * HID + cq + 4 * i];
    }
    __syncthreads();

    float acc2[4][4];
#pragma unroll
    for (int r = 0; r < 4; r++)
#pragma unroll
        for (int c = 0; c < 4; c++) acc2[r][c] = 0.f;
#pragma unroll 4
    for (int k = 0; k < 64; k++) {
        float a[4], w[4];
#pragma unroll
        for (int r = 0; r < 4; r++) a[r] = bufB[(ty + 16 * r) * 68 + k];
#pragma unroll
        for (int c = 0; c < 4; c++) w[c] = bufA[k * 68 + tx + 16 * c];
#pragma unroll
        for (int r = 0; r < 4; r++)
#pragma unroll
            for (int c = 0; c < 4; c++) acc2[r][c] = fmaf(a[r], w[c], acc2[r][c]);
    }
    __syncthreads();
#pragma unroll
    for (int r = 0; r < 4; r++)
#pragma unroll
        for (int c = 0; c < 4; c++)
            bufA[(ty + 16 * r) * 68 + tx + 16 * c] =
                fmaxf(acc2[r][c] + b0[tx + 16 * c], 0.f);

    for (int cb = 0; cb < COMM; cb += 64) {
        {
            int k = t >> 2, cq = (t & 3) * 16;
#pragma unroll
            for (int i = 0; i < 4; i++)
                *(float4*)&bufB[k * 68 + cq + 4 * i] =
                    *(const float4*)&W1[k * COMM + cb + cq + 4 * i];
        }
        __syncthreads();
        float acc3[4][4];
#pragma unroll
        for (int r = 0; r < 4; r++)
#pragma unroll
            for (int c = 0; c < 4; c++) acc3[r][c] = 0.f;
#pragma unroll 4
        for (int k = 0; k < 64; k++) {
            float a[4], w[4];
#pragma unroll
            for (int r = 0; r < 4; r++) a[r] = bufA[(ty + 16 * r) * 68 + k];
#pragma unroll
            for (int c = 0; c < 4; c++) w[c] = bufB[k * 68 + tx + 16 * c];
#pragma unroll
            for (int r = 0; r < 4; r++)
#pragma unroll
                for (int c = 0; c < 4; c++) acc3[r][c] = fmaf(a[r], w[c], acc3[r][c]);
        }
#pragma unroll
        for (int r = 0; r < 4; r++)
#pragma unroll
            for (int c = 0; c < 4; c++)
                g_h3[(rowbase + ty + 16 * r) * COMM + cb + tx + 16 * c] =
                    fmaxf(acc3[r][c] + b1[cb + tx + 16 * c], 0.f);
        __syncthreads();
    }
}

// ---------- variational head: 16 rows / block (validated, 351-357us) ----------
__global__ __launch_bounds__(256) void k_head(
    const float* __restrict__ eps,
    const float* __restrict__ Wm, const float* __restrict__ bm,
    const float* __restrict__ Wv, const float* __restrict__ bv)
{
    __shared__ float  sH[16 * 256];
    __shared__ double sdk[8];
    const int t = threadIdx.x;
    const int rowbase = blockIdx.x * 16;

    if (t < 16) g_cnt[rowbase + t] = 0;

#pragma unroll
    for (int i = 0; i < 4; i++) {
        int f = i * 256 + t;
        int row = f >> 6, c4 = f & 63;
        *(float4*)&sH[row * 256 + c4 * 4] =
            *(const float4*)&g_h3[(rowbase + row) * COMM + c4 * 4];
    }
    __syncthreads();

    const int c = t;
    float ma[16], la[16];
#pragma unroll
    for (int r = 0; r < 16; r++) { ma[r] = 0.f; la[r] = 0.f; }
    for (int k = 0; k < COMM; k++) {
        float w = Wm[k * COMM + c];
#pragma unroll
        for (int r = 0; r < 16; r++) ma[r] = fmaf(sH[r * 256 + k], w, ma[r]);
    }
    for (int k = 0; k < COMM; k++) {
        float w = Wv[k * COMM + c];
#pragma unroll
        for (int r = 0; r < 16; r++) la[r] = fmaf(sH[r * 256 + k], w, la[r]);
    }
    __syncthreads();

    const float bmc = bm[c], bvc = bv[c];
    double dk = 0.0;
#pragma unroll
    for (int r = 0; r < 16; r++) {
        float mu = __fadd_rn(ma[r], bmc);
        float lv = __fadd_rn(la[r], bvc);
        float e  = eps[(rowbase + r) * COMM + c];
        float s  = __fadd_rn(mu, __fmul_rn(e, expf(0.5f * lv)));
        g_sample[(rowbase + r) * COMM + c] = s;
        g_sbf[(rowbase + r) * COMM + c]    = __float2bfloat16_rn(s);
        dk += (double)(1.0f + lv - mu * mu - expf(lv));
        sH[r * 256 + c] = s * s;
    }
    __syncthreads();

    int w = t >> 5, lane = t & 31;
#pragma unroll
    for (int h = 0; h < 2; h++) {
        int r = w + 8 * h;
        float a = 0.f;
#pragma unroll
        for (int m = 0; m < 8; m++) a += sH[r * 256 + lane + 32 * m];
#pragma unroll
        for (int o = 16; o > 0; o >>= 1) a += __shfl_down_sync(0xffffffffu, a, o);
        if (lane == 0) g_sq[rowbase + r] = a;
    }

#pragma unroll
    for (int o = 16; o > 0; o >>= 1) dk += __shfl_down_sync(0xffffffffu, dk, o);
    if (lane == 0) sdk[w] = dk;
    __syncthreads();
    if (t == 0) {
        double v = 0.0;
#pragma unroll
        for (int i = 0; i < 8; i++) v += sdk[i];
        atomicAdd(&g_acc[1], v);
    }
}

// ---------- single-pass bf16 HMMA distance, K=64 per sync, cp.async 4-stage ring ----------
// 256 blocks x 256 threads; 256 iterations (4 k-windows x 64 proto blocks).
__global__ __launch_bounds__(256) void k_dist_hmma()
{
    extern __shared__ __align__(16) char smDyn[];     // STAGES * STAGEB
    __shared__ float sRed[128 * 4];
    const int t = threadIdx.x;
    const int lane = t & 31, wid = t >> 5;
    const int wm = wid >> 2, wn = wid & 3;
    const int g = lane >> 2, tg = lane & 3;
    const int rowbase = blockIdx.x * 128;

    int   rowloc[8];
    float runmin[8], delta[8];
    const float pnm = sqrtf(__uint_as_float(g_pnmax_u));
#pragma unroll
    for (int i = 0; i < 8; i++) {
        int mt = i >> 1, h = i & 1;
        rowloc[i] = wm * 64 + mt * 16 + g + 8 * h;
        float sq = g_sq[rowbase + rowloc[i]];
        delta[i]  = 0.0082f * sqrtf(sq) * pnm + 2e-6f * sq + 1e-6f;
        runmin[i] = 3.4e38f;
    }

    const int r2 = t >> 1, hf = t & 1;
    // thread copies 64B of A and 64B of B per stage: row r2, k-bytes [w2*128+hf*64, +64)
    const char* gA  = (const char*)g_sbf + (size_t)(rowbase + r2) * 512 + hf * 64;
    const char* gB0 = (const char*)g_pbf + (size_t)r2 * 512 + hf * 64;
    const int smo = r2 * ROWB + hf * 64;

    float acc[4][4][4];
#pragma unroll
    for (int mt = 0; mt < 4; mt++)
#pragma unroll
        for (int nt = 0; nt < 4; nt++)
#pragma unroll
            for (int q = 0; q < 4; q++) acc[mt][nt][q] = 0.f;

    // stage issuer: gmem -> smem ring buffer, one commit group per stage
#define ISSUE_STAGE(st) do {                                                         \
        int w2 = (st) & 3, nb2 = (st) >> 2;                                          \
        const char* a2 = gA + w2 * 128;                                              \
        const char* b2 = gB0 + (size_t)nb2 * 128 * 512 + w2 * 128;                   \
        char* buf = smDyn + ((st) & (STAGES - 1)) * STAGEB;                          \
        unsigned sa = (unsigned)__cvta_generic_to_shared(buf + smo);                 \
        unsigned sb = (unsigned)__cvta_generic_to_shared(buf + TILEB + smo);         \
        asm volatile("cp.async.cg.shared.global [%0], [%1], 16;\n" :: "r"(sa),      "l"(a2));      \
        asm volatile("cp.async.cg.shared.global [%0], [%1], 16;\n" :: "r"(sa + 16), "l"(a2 + 16)); \
        asm volatile("cp.async.cg.shared.global [%0], [%1], 16;\n" :: "r"(sa + 32), "l"(a2 + 32)); \
        asm volatile("cp.async.cg.shared.global [%0], [%1], 16;\n" :: "r"(sa + 48), "l"(a2 + 48)); \
        asm volatile("cp.async.cg.shared.global [%0], [%1], 16;\n" :: "r"(sb),      "l"(b2));      \
        asm volatile("cp.async.cg.shared.global [%0], [%1], 16;\n" :: "r"(sb + 16), "l"(b2 + 16)); \
        asm volatile("cp.async.cg.shared.global [%0], [%1], 16;\n" :: "r"(sb + 32), "l"(b2 + 32)); \
        asm volatile("cp.async.cg.shared.global [%0], [%1], 16;\n" :: "r"(sb + 48), "l"(b2 + 48)); \
        asm volatile("cp.async.commit_group;\n");                                    \
    } while (0)

    ISSUE_STAGE(0);
    ISSUE_STAGE(1);
    ISSUE_STAGE(2);

#pragma unroll 1
    for (int it = 0; it < 256; ++it) {
        const int w8 = it & 3, nb = it >> 2;
        // wait until stage `it` has landed (exact tail counts)
        if (it < 254)       asm volatile("cp.async.wait_group 2;\n" ::: "memory");
        else if (it == 254) asm volatile("cp.async.wait_group 1;\n" ::: "memory");
        else                asm volatile("cp.async.wait_group 0;\n" ::: "memory");
        __syncthreads();

        char* bufp = smDyn + (it & (STAGES - 1)) * STAGEB;

        // refill: stage it+3 overwrites the buffer consumed in iteration it-1
        if (it + 3 < 256) ISSUE_STAGE(it + 3);

        // four K=16 steps per buffer
#pragma unroll
        for (int ks = 0; ks < 4; ks++) {
            unsigned a[4][4], bfr[4][2];
#pragma unroll
            for (int mt = 0; mt < 4; mt++) {
                int r  = wm * 64 + mt * 16 + (lane & 15);
                int ch = ks * 2 + (lane >> 4);
                unsigned ad = (unsigned)__cvta_generic_to_shared(bufp + r * ROWB + ch * 16);
                asm volatile("ldmatrix.sync.aligned.m8n8.x4.shared.b16 {%0,%1,%2,%3},[%4];"
                    : "=r"(a[mt][0]), "=r"(a[mt][1]), "=r"(a[mt][2]), "=r"(a[mt][3]) : "r"(ad));
            }
#pragma unroll
            for (int nt = 0; nt < 4; nt++) {
                int l  = lane & 15;
                int n  = wn * 32 + nt * 8 + (l & 7);
                int ch = ks * 2 + (l >> 3);
                unsigned ad = (unsigned)__cvta_generic_to_shared(bufp + TILEB + n * ROWB + ch * 16);
                asm volatile("ldmatrix.sync.aligned.m8n8.x2.shared.b16 {%0,%1},[%2];"
                    : "=r"(bfr[nt][0]), "=r"(bfr[nt][1]) : "r"(ad));
            }
#pragma unroll
            for (int mt = 0; mt < 4; mt++)
#pragma unroll
                for (int nt = 0; nt < 4; nt++)
                    asm volatile(
                        "mma.sync.aligned.m16n8k16.row.col.f32.bf16.bf16.f32 "
                        "{%0,%1,%2,%3},{%4,%5,%6,%7},{%8,%9},{%0,%1,%2,%3};"
                        : "+f"(acc[mt][nt][0]), "+f"(acc[mt][nt][1]),
                          "+f"(acc[mt][nt][2]), "+f"(acc[mt][nt][3])
                        : "r"(a[mt][0]), "r"(a[mt][1]), "r"(a[mt][2]), "r"(a[mt][3]),
                          "r"(bfr[nt][0]), "r"(bfr[nt][1]));
        }

        if (w8 == 3) {
            const int jbase = nb * 128;
            float tmin[8];
#pragma unroll
            for (int i = 0; i < 8; i++) tmin[i] = 3.4e38f;
#pragma unroll
            for (int nt = 0; nt < 4; nt++) {
                int j0 = jbase + wn * 32 + nt * 8 + 2 * tg;
                float pn0 = __ldg(&g_pn[j0]), pn1 = __ldg(&g_pn[j0 + 1]);
#pragma unroll
                for (int mt = 0; mt < 4; mt++) {
                    acc[mt][nt][0] = fmaf(-2.f, acc[mt][nt][0], pn0);
                    acc[mt][nt][1] = fmaf(-2.f, acc[mt][nt][1], pn1);
                    acc[mt][nt][2] = fmaf(-2.f, acc[mt][nt][2], pn0);
                    acc[mt][nt][3] = fmaf(-2.f, acc[mt][nt][3], pn1);
                    tmin[mt * 2]     = fminf(tmin[mt * 2],
                                             fminf(acc[mt][nt][0], acc[mt][nt][1]));
                    tmin[mt * 2 + 1] = fminf(tmin[mt * 2 + 1],
                                             fminf(acc[mt][nt][2], acc[mt][nt][3]));
                }
            }
#pragma unroll
            for (int i = 0; i < 8; i++) {
                tmin[i] = fminf(tmin[i], __shfl_xor_sync(0xffffffffu, tmin[i], 1));
                tmin[i] = fminf(tmin[i], __shfl_xor_sync(0xffffffffu, tmin[i], 2));
            }
            if (tg == 0) {
#pragma unroll
                for (int i = 0; i < 8; i++) sRed[rowloc[i] * 4 + wn] = tmin[i];
            }
            __syncthreads();
            float th[8];
#pragma unroll
            for (int i = 0; i < 8; i++) {
                float tm = fminf(fminf(sRed[rowloc[i] * 4 + 0], sRed[rowloc[i] * 4 + 1]),
                                 fminf(sRed[rowloc[i] * 4 + 2], sRed[rowloc[i] * 4 + 3]));
                float m = fminf(runmin[i], tm);
                th[i] = m + delta[i];
                runmin[i] = m;
            }
#pragma unroll
            for (int nt = 0; nt < 4; nt++) {
                int j0 = jbase + wn * 32 + nt * 8 + 2 * tg;
#pragma unroll
                for (int mt = 0; mt < 4; mt++) {
                    int i0 = mt * 2, i1 = mt * 2 + 1;
                    int row0 = rowbase + rowloc[i0];
                    int row1 = rowbase + rowloc[i1];
                    if (acc[mt][nt][0] <= th[i0]) { int sl = atomicAdd(&g_cnt[row0], 1); if (sl < MAXC) g_cand[row0 * MAXC + sl] = j0; }
                    if (acc[mt][nt][1] <= th[i0]) { int sl = atomicAdd(&g_cnt[row0], 1); if (sl < MAXC) g_cand[row0 * MAXC + sl] = j0 + 1; }
                    if (acc[mt][nt][2] <= th[i1]) { int sl = atomicAdd(&g_cnt[row1], 1); if (sl < MAXC) g_cand[row1 * MAXC + sl] = j0; }
                    if (acc[mt][nt][3] <= th[i1]) { int sl = atomicAdd(&g_cnt[row1], 1); if (sl < MAXC) g_cand[row1 * MAXC + sl] = j0 + 1; }
                    acc[mt][nt][0] = 0.f; acc[mt][nt][1] = 0.f;
                    acc[mt][nt][2] = 0.f; acc[mt][nt][3] = 0.f;
                }
            }
            __syncthreads();
        }
    }
#undef ISSUE_STAGE
}

// ---------- exact fp32 rescue: resolve argmin among candidates ----------
__global__ __launch_bounds__(256) void k_resolve(const float* __restrict__ protos)
{
    const int wid = threadIdx.x >> 5, lane = threadIdx.x & 31;
    const int row = blockIdx.x * 8 + wid;
    const int cnt = g_cnt[row];
    if (cnt == 1) {
        if (lane == 0) g_idx[row] = g_cand[row * MAXC];
        return;
    }
    const float* s = &g_sample[(size_t)row * COMM];
    const float sq = g_sq[row];
    float bd = 3.4e38f; int bj = 0x7fffffff;
    if (cnt >= 2 && cnt <= MAXC) {
        for (int c = lane; c < cnt; c += 32) {
            int j = g_cand[row * MAXC + c];
            const float* p = &protos[(size_t)j * COMM];
            float acc = 0.f;
            for (int k = 0; k < COMM; k++) acc = fmaf(s[k], p[k], acc);
            float t1 = __fadd_rn(sq, g_pn[j]);
            float d  = __fadd_rn(t1, -__fmul_rn(2.0f, acc));
            if (d < bd || (d == bd && j < bj)) { bd = d; bj = j; }
        }
    } else {   // cnt == 0 (shouldn't happen) or overflow: exact full scan
        for (int j = lane; j < KP; j += 32) {
            const float* p = &protos[(size_t)j * COMM];
            float acc = 0.f;
            for (int k = 0; k < COMM; k++) acc = fmaf(s[k], p[k], acc);
            float t1 = __fadd_rn(sq, g_pn[j]);
            float d  = __fadd_rn(t1, -__fmul_rn(2.0f, acc));
            if (d < bd) { bd = d; bj = j; }
        }
    }
#pragma unroll
    for (int o = 16; o > 0; o >>= 1) {
        float od = __shfl_xor_sync(0xffffffffu, bd, o);
        int   oj = __shfl_xor_sync(0xffffffffu, bj, o);
        if (od < bd || (od == bd && oj < bj)) { bd = od; bj = oj; }
    }
    if (lane == 0) g_idx[row] = bj;
}

// ---------- gather q, write q_st, accumulate (q-s)^2 ----------
__global__ __launch_bounds__(256) void k_final(const float* __restrict__ protos,
                                               float* __restrict__ out)
{
    __shared__ double sdk[8];
    const int t = threadIdx.x;
    const int rowbase = blockIdx.x * 32;
    double s2 = 0.0;
    for (int r = 0; r < 32; r++) {
        int row = rowbase + r;
        int idx = g_idx[row];
        float q    = protos[idx * COMM + t];
        float s    = g_sample[row * COMM + t];
        float diff = __fsub_rn(q, s);
        out[row * COMM + t] = __fadd_rn(s, diff);
        s2 += (double)diff * (double)diff;
    }
    int w = t >> 5, lane = t & 31;
#pragma unroll
    for (int o = 16; o > 0; o >>= 1) s2 += __shfl_down_sync(0xffffffffu, s2, o);
    if (lane == 0) sdk[w] = s2;
    __syncthreads();
    if (t == 0) {
        double v = 0.0;
#pragma unroll
        for (int i = 0; i < 8; i++) v += sdk[i];
        atomicAdd(&g_acc[0], v);
    }
}

// ---------- scalars ----------
__global__ void k_scalar(float* __restrict__ out, int out_size)
{
    double m   = g_acc[0] / ((double)B_ROWS * (double)COMM);
    double kld = -0.5 * g_acc[1] / (double)B_ROWS;
    double total = kld + 1.25 * m;
    out[out_size - 2] = (float)total;
    out[out_size - 1] = (float)kld;
}

extern "C" void kernel_launch(void* const* d_in, const int* in_sizes, int n_in,
                              void* d_out, int out_size)
{
    const float* x      = (const float*)d_in[0];
    const float* eps    = (const float*)d_in[1];
    const float* W_feat = (const float*)d_in[2];
    const float* b_feat = (const float*)d_in[3];
    const float* W0     = (const float*)d_in[4];
    const float* b0     = (const float*)d_in[5];
    const float* W1     = (const float*)d_in[6];
    const float* b1     = (const float*)d_in[7];
    const float* W_mu   = (const float*)d_in[8];
    const float* b_mu   = (const float*)d_in[9];
    const float* W_var  = (const float*)d_in[10];
    const float* b_var  = (const float*)d_in[11];
    const float* protos = (const float*)d_in[12];
    float* out = (float*)d_out;

    cudaFuncSetAttribute(k_dist_hmma, cudaFuncAttributeMaxDynamicSharedMemorySize, DSMEM);

    k_pn<<<KP / 8, 256>>>(protos);
    k_mlp<<<B_ROWS / 64, 256>>>(x, W_feat, b_feat, W0, b0, W1, b1);
    k_head<<<B_ROWS / 16, 256>>>(eps, W_mu, b_mu, W_var, b_var);
    k_dist_hmma<<<B_ROWS / 128, 256, DSMEM>>>();
    k_resolve<<<B_ROWS / 8, 256>>>(protos);
    k_final<<<B_ROWS / 32, 256>>>(protos, out);
    k_scalar<<<1, 1>>>(out, out_size);
}

// round 15
// speedup vs baseline: 1.2415x; 1.2415x over previous
#include <cuda_runtime.h>
#include <cuda_bf16.h>
#include <math.h>
#include <stdint.h>

#define B_ROWS 32768
#define IN_DIM 1024
#define HID    64
#define COMM   256
#define KP     8192
#define MAXC   48

#define ROWB   80      // dist smem row stride: 64B data (K=32 bf16) + 16B pad
#define TILEB  10240   // 128 rows * 80B
#define STAGEB (2 * TILEB)      // A tile + B tile per stage
#define STAGES 4
#define DSMEM  (STAGES * STAGEB)   // 81920 dynamic smem

// ---------- scratch (no runtime allocation allowed) ----------
__device__ float  g_h3[B_ROWS * COMM];
__device__ float  g_sample[B_ROWS * COMM];
__device__ __nv_bfloat16 g_sbf[B_ROWS * COMM];
__device__ __nv_bfloat16 g_pbf[KP * COMM];
__device__ float  g_sq[B_ROWS];
__device__ float  g_pn[KP];
__device__ unsigned int g_pnmax_u;   // monotone: atomicMax is idempotent across replays
__device__ int    g_cnt[B_ROWS];
__device__ int    g_cand[B_ROWS * MAXC];
__device__ int    g_idx[B_ROWS];
__device__ double g_acc[2];

// ---------- proto squared norms + bf16 conversion (+ accumulator zeroing) ----------
__global__ void k_pn(const float* __restrict__ protos) {
    if (blockIdx.x == 0 && threadIdx.x == 0) { g_acc[0] = 0.0; g_acc[1] = 0.0; }
    int row  = blockIdx.x * 8 + (threadIdx.x >> 5);
    int lane = threadIdx.x & 31;
    float a = 0.f;
#pragma unroll
    for (int m = 0; m < 8; m++) {
        float v = protos[row * COMM + lane + 32 * m];
        g_pbf[row * COMM + lane + 32 * m] = __float2bfloat16_rn(v);
        a = fmaf(v, v, a);
    }
#pragma unroll
    for (int o = 16; o > 0; o >>= 1) a += __shfl_down_sync(0xffffffffu, a, o);
    if (lane == 0) {
        g_pn[row] = a;
        atomicMax(&g_pnmax_u, __float_as_uint(a));
    }
}

// ---------- fused MLP (unchanged, validated) ----------
__global__ __launch_bounds__(256) void k_mlp(
    const float* __restrict__ x,  const float* __restrict__ Wf, const float* __restrict__ bf,
    const float* __restrict__ W0, const float* __restrict__ b0,
    const float* __restrict__ W1, const float* __restrict__ b1)
{
    __shared__ float bufA[64 * 68];
    __shared__ float bufB[64 * 68];
    const int t  = threadIdx.x;
    const int tx = t & 15, ty = t >> 4;
    const int rowbase = blockIdx.x * 64;

    float* sX = bufA;
    float* sW = bufA + 32 * 68;

    float acc[4][4];
#pragma unroll
    for (int r = 0; r < 4; r++)
#pragma unroll
        for (int c = 0; c < 4; c++) acc[r][c] = 0.f;

    for (int kc = 0; kc < IN_DIM; kc += 32) {
        {
            int row = t >> 2, kq = (t & 3) * 8;
            const float* src = &x[(rowbase + row) * IN_DIM + kc + kq];
            float4 v0 = *(const float4*)(src);
            float4 v1 = *(const float4*)(src + 4);
            sX[(kq + 0) * 68 + row] = v0.x; sX[(kq + 1) * 68 + row] = v0.y;
            sX[(kq + 2) * 68 + row] = v0.z; sX[(kq + 3) * 68 + row] = v0.w;
            sX[(kq + 4) * 68 + row] = v1.x; sX[(kq + 5) * 68 + row] = v1.y;
            sX[(kq + 6) * 68 + row] = v1.z; sX[(kq + 7) * 68 + row] = v1.w;
            int k = t >> 3, cq = (t & 7) * 8;
            const float* ws = &Wf[(kc + k) * HID + cq];
            float4 w0 = *(const float4*)(ws);
            float4 w1 = *(const float4*)(ws + 4);
            *(float4*)&sW[k * 68 + cq]     = w0;
            *(float4*)&sW[k * 68 + cq + 4] = w1;
        }
        __syncthreads();
#pragma unroll 8
        for (int k = 0; k < 32; k++) {
            float a[4], w[4];
#pragma unroll
            for (int r = 0; r < 4; r++) a[r] = sX[k * 68 + ty + 16 * r];
#pragma unroll
            for (int c = 0; c < 4; c++) w[c] = sW[k * 68 + tx + 16 * c];
#pragma unroll
            for (int r = 0; r < 4; r++)
#pragma unroll
                for (int c = 0; c < 4; c++) acc[r][c] = fmaf(a[r], w[c], acc[r][c]);
        }
        __syncthreads();
    }
#pragma unroll
    for (int r = 0; r < 4; r++)
#pragma unroll
        for (int c = 0; c < 4; c++)
            bufB[(ty + 16 * r) * 68 + tx + 16 * c] = acc[r][c] + bf[tx + 16 * c];

    {
        int k = t >> 2, cq = (t & 3) * 16;
#pragma unroll
        for (int i = 0; i < 4; i++)
            *(float4*)&bufA[k * 68 + cq + 4 * i] = *(const float4*)&W0[k * HID + cq + 4 * i];
    }
    __syncthreads();

    float acc2[4][4];
#pragma unroll
    for (int r = 0; r < 4; r++)
#pragma unroll
        for (int c = 0; c < 4; c++) acc2[r][c] = 0.f;
#pragma unroll 4
    for (int k = 0; k < 64; k++) {
        float a[4], w[4];
#pragma unroll
        for (int r = 0; r < 4; r++) a[r] = bufB[(ty + 16 * r) * 68 + k];
#pragma unroll
        for (int c = 0; c < 4; c++) w[c] = bufA[k * 68 + tx + 16 * c];
#pragma unroll
        for (int r = 0; r < 4; r++)
#pragma unroll
            for (int c = 0; c < 4; c++) acc2[r][c] = fmaf(a[r], w[c], acc2[r][c]);
    }
    __syncthreads();
#pragma unroll
    for (int r = 0; r < 4; r++)
#pragma unroll
        for (int c = 0; c < 4; c++)
            bufA[(ty + 16 * r) * 68 + tx + 16 * c] =
                fmaxf(acc2[r][c] + b0[tx + 16 * c], 0.f);

    for (int cb = 0; cb < COMM; cb += 64) {
        {
            int k = t >> 2, cq = (t & 3) * 16;
#pragma unroll
            for (int i = 0; i < 4; i++)
                *(float4*)&bufB[k * 68 + cq + 4 * i] =
                    *(const float4*)&W1[k * COMM + cb + cq + 4 * i];
        }
        __syncthreads();
        float acc3[4][4];
#pragma unroll
        for (int r = 0; r < 4; r++)
#pragma unroll
            for (int c = 0; c < 4; c++) acc3[r][c] = 0.f;
#pragma unroll 4
        for (int k = 0; k < 64; k++) {
            float a[4], w[4];
#pragma unroll
            for (int r = 0; r < 4; r++) a[r] = bufA[(ty + 16 * r) * 68 + k];
#pragma unroll
            for (int c = 0; c < 4; c++) w[c] = bufB[k * 68 + tx + 16 * c];
#pragma unroll
            for (int r = 0; r < 4; r++)
#pragma unroll
                for (int c = 0; c < 4; c++) acc3[r][c] = fmaf(a[r], w[c], acc3[r][c]);
        }
#pragma unroll
        for (int r = 0; r < 4; r++)
#pragma unroll
            for (int c = 0; c < 4; c++)
                g_h3[(rowbase + ty + 16 * r) * COMM + cb + tx + 16 * c] =
                    fmaxf(acc3[r][c] + b1[cb + tx + 16 * c], 0.f);
        __syncthreads();
    }
}

// ---------- variational head: 16 rows / block (validated, 351-357us) ----------
__global__ __launch_bounds__(256) void k_head(
    const float* __restrict__ eps,
    const float* __restrict__ Wm, const float* __restrict__ bm,
    const float* __restrict__ Wv, const float* __restrict__ bv)
{
    __shared__ float  sH[16 * 256];
    __shared__ double sdk[8];
    const int t = threadIdx.x;
    const int rowbase = blockIdx.x * 16;

    if (t < 16) g_cnt[rowbase + t] = 0;

#pragma unroll
    for (int i = 0; i < 4; i++) {
        int f = i * 256 + t;
        int row = f >> 6, c4 = f & 63;
        *(float4*)&sH[row * 256 + c4 * 4] =
            *(const float4*)&g_h3[(rowbase + row) * COMM + c4 * 4];
    }
    __syncthreads();

    const int c = t;
    float ma[16], la[16];
#pragma unroll
    for (int r = 0; r < 16; r++) { ma[r] = 0.f; la[r] = 0.f; }
    for (int k = 0; k < COMM; k++) {
        float w = Wm[k * COMM + c];
#pragma unroll
        for (int r = 0; r < 16; r++) ma[r] = fmaf(sH[r * 256 + k], w, ma[r]);
    }
    for (int k = 0; k < COMM; k++) {
        float w = Wv[k * COMM + c];
#pragma unroll
        for (int r = 0; r < 16; r++) la[r] = fmaf(sH[r * 256 + k], w, la[r]);
    }
    __syncthreads();

    const float bmc = bm[c], bvc = bv[c];
    double dk = 0.0;
#pragma unroll
    for (int r = 0; r < 16; r++) {
        float mu = __fadd_rn(ma[r], bmc);
        float lv = __fadd_rn(la[r], bvc);
        float e  = eps[(rowbase + r) * COMM + c];
        float s  = __fadd_rn(mu, __fmul_rn(e, expf(0.5f * lv)));
        g_sample[(rowbase + r) * COMM + c] = s;
        g_sbf[(rowbase + r) * COMM + c]    = __float2bfloat16_rn(s);
        dk += (double)(1.0f + lv - mu * mu - expf(lv));
        sH[r * 256 + c] = s * s;
    }
    __syncthreads();

    int w = t >> 5, lane = t & 31;
#pragma unroll
    for (int h = 0; h < 2; h++) {
        int r = w + 8 * h;
        float a = 0.f;
#pragma unroll
        for (int m = 0; m < 8; m++) a += sH[r * 256 + lane + 32 * m];
#pragma unroll
        for (int o = 16; o > 0; o >>= 1) a += __shfl_down_sync(0xffffffffu, a, o);
        if (lane == 0) g_sq[rowbase + r] = a;
    }

#pragma unroll
    for (int o = 16; o > 0; o >>= 1) dk += __shfl_down_sync(0xffffffffu, dk, o);
    if (lane == 0) sdk[w] = dk;
    __syncthreads();
    if (t == 0) {
        double v = 0.0;
#pragma unroll
        for (int i = 0; i < 8; i++) v += sdk[i];
        atomicAdd(&g_acc[1], v);
    }
}

// ---------- single-pass bf16 HMMA distance: 512 threads, 32x32 warp tiles ----------
// 256 blocks x 512 threads; 512 iterations (8 k-windows x 64 proto blocks).
// 16 warps: wm=wid>>2 picks 32-row band, wn=wid&3 picks 32-col band.
__global__ __launch_bounds__(512) void k_dist_hmma()
{
    extern __shared__ __align__(16) char smDyn[];     // STAGES * STAGEB
    __shared__ float sRed[128 * 4];
    const int t = threadIdx.x;
    const int lane = t & 31, wid = t >> 5;
    const int wm = wid >> 2, wn = wid & 3;
    const int g = lane >> 2, tg = lane & 3;
    const int rowbase = blockIdx.x * 128;

    int   rowloc[4];
    float runmin[4], delta[4];
    const float pnm = sqrtf(__uint_as_float(g_pnmax_u));
#pragma unroll
    for (int i = 0; i < 4; i++) {
        int mt = i >> 1, h = i & 1;
        rowloc[i] = wm * 32 + mt * 16 + g + 8 * h;
        float sq = g_sq[rowbase + rowloc[i]];
        delta[i]  = 0.0082f * sqrtf(sq) * pnm + 2e-6f * sq + 1e-6f;
        runmin[i] = 3.4e38f;
    }

    // each thread copies ONE 16B chunk of A and ONE of B per stage
    const int cr = t >> 2, cc = t & 3;        // row 0-127, chunk 0-3
    const char* gA  = (const char*)g_sbf + (size_t)(rowbase + cr) * 512 + cc * 16;
    const char* gB0 = (const char*)g_pbf + (size_t)cr * 512 + cc * 16;
    const int smo = cr * ROWB + cc * 16;

    float acc[2][4][4];
#pragma unroll
    for (int mt = 0; mt < 2; mt++)
#pragma unroll
        for (int nt = 0; nt < 4; nt++)
#pragma unroll
            for (int q = 0; q < 4; q++) acc[mt][nt][q] = 0.f;

    // stage issuer: gmem -> smem ring buffer, one commit group per stage
#define ISSUE_STAGE(st) do {                                                         \
        int w2 = (st) & 7, nb2 = (st) >> 3;                                          \
        const char* a2 = gA + w2 * 64;                                               \
        const char* b2 = gB0 + (size_t)nb2 * 128 * 512 + w2 * 64;                    \
        char* buf = smDyn + ((st) & (STAGES - 1)) * STAGEB;                          \
        unsigned sa = (unsigned)__cvta_generic_to_shared(buf + smo);                 \
        unsigned sb = (unsigned)__cvta_generic_to_shared(buf + TILEB + smo);         \
        asm volatile("cp.async.cg.shared.global [%0], [%1], 16;\n"                   \
                     :: "r"(sa), "l"(a2));                                           \
        asm volatile("cp.async.cg.shared.global [%0], [%1], 16;\n"                   \
                     :: "r"(sb), "l"(b2));                                           \
        asm volatile("cp.async.commit_group;\n");                                    \
    } while (0)

    ISSUE_STAGE(0);
    ISSUE_STAGE(1);
    ISSUE_STAGE(2);

#pragma unroll 1
    for (int it = 0; it < 512; ++it) {
        const int w8 = it & 7, nb = it >> 3;
        // wait until stage `it` has landed (exact tail counts)
        if (it < 510)       asm volatile("cp.async.wait_group 2;\n" ::: "memory");
        else if (it == 510) asm volatile("cp.async.wait_group 1;\n" ::: "memory");
        else                asm volatile("cp.async.wait_group 0;\n" ::: "memory");
        __syncthreads();

        char* bufp = smDyn + (it & (STAGES - 1)) * STAGEB;

        // refill: stage it+3 overwrites the buffer consumed in iteration it-1
        if (it + 3 < 512) ISSUE_STAGE(it + 3);

        // two K=16 steps per buffer
#pragma unroll
        for (int ks = 0; ks < 2; ks++) {
            unsigned a[2][4], bfr[4][2];
#pragma unroll
            for (int mt = 0; mt < 2; mt++) {
                int r  = wm * 32 + mt * 16 + (lane & 15);
                int ch = ks * 2 + (lane >> 4);
                unsigned ad = (unsigned)__cvta_generic_to_shared(bufp + r * ROWB + ch * 16);
                asm volatile("ldmatrix.sync.aligned.m8n8.x4.shared.b16 {%0,%1,%2,%3},[%4];"
                    : "=r"(a[mt][0]), "=r"(a[mt][1]), "=r"(a[mt][2]), "=r"(a[mt][3]) : "r"(ad));
            }
#pragma unroll
            for (int nt = 0; nt < 4; nt++) {
                int l  = lane & 15;
                int n  = wn * 32 + nt * 8 + (l & 7);
                int ch = ks * 2 + (l >> 3);
                unsigned ad = (unsigned)__cvta_generic_to_shared(bufp + TILEB + n * ROWB + ch * 16);
                asm volatile("ldmatrix.sync.aligned.m8n8.x2.shared.b16 {%0,%1},[%2];"
                    : "=r"(bfr[nt][0]), "=r"(bfr[nt][1]) : "r"(ad));
            }
#pragma unroll
            for (int mt = 0; mt < 2; mt++)
#pragma unroll
                for (int nt = 0; nt < 4; nt++)
                    asm volatile(
                        "mma.sync.aligned.m16n8k16.row.col.f32.bf16.bf16.f32 "
                        "{%0,%1,%2,%3},{%4,%5,%6,%7},{%8,%9},{%0,%1,%2,%3};"
                        : "+f"(acc[mt][nt][0]), "+f"(acc[mt][nt][1]),
                          "+f"(acc[mt][nt][2]), "+f"(acc[mt][nt][3])
                        : "r"(a[mt][0]), "r"(a[mt][1]), "r"(a[mt][2]), "r"(a[mt][3]),
                          "r"(bfr[nt][0]), "r"(bfr[nt][1]));
        }

        if (w8 == 7) {
            const int jbase = nb * 128;
            float tmin[4];
#pragma unroll
            for (int i = 0; i < 4; i++) tmin[i] = 3.4e38f;
#pragma unroll
            for (int nt = 0; nt < 4; nt++) {
                int j0 = jbase + wn * 32 + nt * 8 + 2 * tg;
                float pn0 = __ldg(&g_pn[j0]), pn1 = __ldg(&g_pn[j0 + 1]);
#pragma unroll
                for (int mt = 0; mt < 2; mt++) {
                    acc[mt][nt][0] = fmaf(-2.f, acc[mt][nt][0], pn0);
                    acc[mt][nt][1] = fmaf(-2.f, acc[mt][nt][1], pn1);
                    acc[mt][nt][2] = fmaf(-2.f, acc[mt][nt][2], pn0);
                    acc[mt][nt][3] = fmaf(-2.f, acc[mt][nt][3], pn1);
                    tmin[mt * 2]     = fminf(tmin[mt * 2],
                                             fminf(acc[mt][nt][0], acc[mt][nt][1]));
                    tmin[mt * 2 + 1] = fminf(tmin[mt * 2 + 1],
                                             fminf(acc[mt][nt][2], acc[mt][nt][3]));
                }
            }
#pragma unroll
            for (int i = 0; i < 4; i++) {
                tmin[i] = fminf(tmin[i], __shfl_xor_sync(0xffffffffu, tmin[i], 1));
                tmin[i] = fminf(tmin[i], __shfl_xor_sync(0xffffffffu, tmin[i], 2));
            }
            if (tg == 0) {
#pragma unroll
                for (int i = 0; i < 4; i++) sRed[rowloc[i] * 4 + wn] = tmin[i];
            }
            __syncthreads();
            float th[4];
#pragma unroll
            for (int i = 0; i < 4; i++) {
                float tm = fminf(fminf(sRed[rowloc[i] * 4 + 0], sRed[rowloc[i] * 4 + 1]),
                                 fminf(sRed[rowloc[i] * 4 + 2], sRed[rowloc[i] * 4 + 3]));
                float m = fminf(runmin[i], tm);
                th[i] = m + delta[i];
                runmin[i] = m;
            }
#pragma unroll
            for (int nt = 0; nt < 4; nt++) {
                int j0 = jbase + wn * 32 + nt * 8 + 2 * tg;
#pragma unroll
                for (int mt = 0; mt < 2; mt++) {
                    int i0 = mt * 2, i1 = mt * 2 + 1;
                    int row0 = rowbase + rowloc[i0];
                    int row1 = rowbase + rowloc[i1];
                    if (acc[mt][nt][0] <= th[i0]) { int sl = atomicAdd(&g_cnt[row0], 1); if (sl < MAXC) g_cand[row0 * MAXC + sl] = j0; }
                    if (acc[mt][nt][1] <= th[i0]) { int sl = atomicAdd(&g_cnt[row0], 1); if (sl < MAXC) g_cand[row0 * MAXC + sl] = j0 + 1; }
                    if (acc[mt][nt][2] <= th[i1]) { int sl = atomicAdd(&g_cnt[row1], 1); if (sl < MAXC) g_cand[row1 * MAXC + sl] = j0; }
                    if (acc[mt][nt][3] <= th[i1]) { int sl = atomicAdd(&g_cnt[row1], 1); if (sl < MAXC) g_cand[row1 * MAXC + sl] = j0 + 1; }
                    acc[mt][nt][0] = 0.f; acc[mt][nt][1] = 0.f;
                    acc[mt][nt][2] = 0.f; acc[mt][nt][3] = 0.f;
                }
            }
            __syncthreads();
        }
    }
#undef ISSUE_STAGE
}

// ---------- exact fp32 rescue: resolve argmin among candidates ----------
__global__ __launch_bounds__(256) void k_resolve(const float* __restrict__ protos)
{
    const int wid = threadIdx.x >> 5, lane = threadIdx.x & 31;
    const int row = blockIdx.x * 8 + wid;
    const int cnt = g_cnt[row];
    if (cnt == 1) {
        if (lane == 0) g_idx[row] = g_cand[row * MAXC];
        return;
    }
    const float* s = &g_sample[(size_t)row * COMM];
    const float sq = g_sq[row];
    float bd = 3.4e38f; int bj = 0x7fffffff;
    if (cnt >= 2 && cnt <= MAXC) {
        for (int c = lane; c < cnt; c += 32) {
            int j = g_cand[row * MAXC + c];
            const float* p = &protos[(size_t)j * COMM];
            float acc = 0.f;
            for (int k = 0; k < COMM; k++) acc = fmaf(s[k], p[k], acc);
            float t1 = __fadd_rn(sq, g_pn[j]);
            float d  = __fadd_rn(t1, -__fmul_rn(2.0f, acc));
            if (d < bd || (d == bd && j < bj)) { bd = d; bj = j; }
        }
    } else {   // cnt == 0 (shouldn't happen) or overflow: exact full scan
        for (int j = lane; j < KP; j += 32) {
            const float* p = &protos[(size_t)j * COMM];
            float acc = 0.f;
            for (int k = 0; k < COMM; k++) acc = fmaf(s[k], p[k], acc);
            float t1 = __fadd_rn(sq, g_pn[j]);
            float d  = __fadd_rn(t1, -__fmul_rn(2.0f, acc));
            if (d < bd) { bd = d; bj = j; }
        }
    }
#pragma unroll
    for (int o = 16; o > 0; o >>= 1) {
        float od = __shfl_xor_sync(0xffffffffu, bd, o);
        int   oj = __shfl_xor_sync(0xffffffffu, bj, o);
        if (od < bd || (od == bd && oj < bj)) { bd = od; bj = oj; }
    }
    if (lane == 0) g_idx[row] = bj;
}

// ---------- gather q, write q_st, accumulate (q-s)^2 ----------
__global__ __launch_bounds__(256) void k_final(const float* __restrict__ protos,
                                               float* __restrict__ out)
{
    __shared__ double sdk[8];
    const int t = threadIdx.x;
    const int rowbase = blockIdx.x * 32;
    double s2 = 0.0;
    for (int r = 0; r < 32; r++) {
        int row = rowbase + r;
        int idx = g_idx[row];
        float q    = protos[idx * COMM + t];
        float s    = g_sample[row * COMM + t];
        float diff = __fsub_rn(q, s);
        out[row * COMM + t] = __fadd_rn(s, diff);
        s2 += (double)diff * (double)diff;
    }
    int w = t >> 5, lane = t & 31;
#pragma unroll
    for (int o = 16; o > 0; o >>= 1) s2 += __shfl_down_sync(0xffffffffu, s2, o);
    if (lane == 0) sdk[w] = s2;
    __syncthreads();
    if (t == 0) {
        double v = 0.0;
#pragma unroll
        for (int i = 0; i < 8; i++) v += sdk[i];
        atomicAdd(&g_acc[0], v);
    }
}

// ---------- scalars ----------
__global__ void k_scalar(float* __restrict__ out, int out_size)
{
    double m   = g_acc[0] / ((double)B_ROWS * (double)COMM);
    double kld = -0.5 * g_acc[1] / (double)B_ROWS;
    double total = kld + 1.25 * m;
    out[out_size - 2] = (float)total;
    out[out_size - 1] = (float)kld;
}

extern "C" void kernel_launch(void* const* d_in, const int* in_sizes, int n_in,
                              void* d_out, int out_size)
{
    const float* x      = (const float*)d_in[0];
    const float* eps    = (const float*)d_in[1];
    const float* W_feat = (const float*)d_in[2];
    const float* b_feat = (const float*)d_in[3];
    const float* W0     = (const float*)d_in[4];
    const float* b0     = (const float*)d_in[5];
    const float* W1     = (const float*)d_in[6];
    const float* b1     = (const float*)d_in[7];
    const float* W_mu   = (const float*)d_in[8];
    const float* b_mu   = (const float*)d_in[9];
    const float* W_var  = (const float*)d_in[10];
    const float* b_var  = (const float*)d_in[11];
    const float* protos = (const float*)d_in[12];
    float* out = (float*)d_out;

    cudaFuncSetAttribute(k_dist_hmma, cudaFuncAttributeMaxDynamicSharedMemorySize, DSMEM);

    k_pn<<<KP / 8, 256>>>(protos);
    k_mlp<<<B_ROWS / 64, 256>>>(x, W_feat, b_feat, W0, b0, W1, b1);
    k_head<<<B_ROWS / 16, 256>>>(eps, W_mu, b_mu, W_var, b_var);
    k_dist_hmma<<<B_ROWS / 128, 512, DSMEM>>>();
    k_resolve<<<B_ROWS / 8, 256>>>(protos);
    k_final<<<B_ROWS / 32, 256>>>(protos, out);
    k_scalar<<<1, 1>>>(out, out_size);
}

// round 16
// speedup vs baseline: 1.2811x; 1.0319x over previous
#include <cuda_runtime.h>
#include <cuda_bf16.h>
#include <math.h>
#include <stdint.h>

#define B_ROWS 32768
#define IN_DIM 1024
#define HID    64
#define COMM   256
#define KP     8192
#define MAXC   48

#define ROWB   80      // dist smem row stride: 64B data (K=32 bf16) + 16B pad
#define TILEB  10240   // 128 rows * 80B
#define STAGEB (2 * TILEB)      // A tile + B tile per stage
#define STAGES 4
#define DSMEM  (STAGES * STAGEB)   // 81920 dynamic smem

// ---------- scratch (no runtime allocation allowed) ----------
__device__ float  g_h3[B_ROWS * COMM];
__device__ float  g_sample[B_ROWS * COMM];
__device__ __nv_bfloat16 g_sbf[B_ROWS * COMM];
__device__ __nv_bfloat16 g_pbf[KP * COMM];
__device__ float  g_sq[B_ROWS];
__device__ float  g_pn[KP];
__device__ unsigned int g_pnmax_u;   // monotone: atomicMax is idempotent across replays
__device__ int    g_cnt[B_ROWS];
__device__ int    g_cand[B_ROWS * MAXC];
__device__ int    g_idx[B_ROWS];
__device__ double g_acc[2];

// ---------- proto squared norms + bf16 conversion (+ accumulator zeroing) ----------
__global__ void k_pn(const float* __restrict__ protos) {
    if (blockIdx.x == 0 && threadIdx.x == 0) { g_acc[0] = 0.0; g_acc[1] = 0.0; }
    int row  = blockIdx.x * 8 + (threadIdx.x >> 5);
    int lane = threadIdx.x & 31;
    float a = 0.f;
#pragma unroll
    for (int m = 0; m < 8; m++) {
        float v = protos[row * COMM + lane + 32 * m];
        g_pbf[row * COMM + lane + 32 * m] = __float2bfloat16_rn(v);
        a = fmaf(v, v, a);
    }
#pragma unroll
    for (int o = 16; o > 0; o >>= 1) a += __shfl_down_sync(0xffffffffu, a, o);
    if (lane == 0) {
        g_pn[row] = a;
        atomicMax(&g_pnmax_u, __float_as_uint(a));
    }
}

// ---------- fused MLP (unchanged, validated) ----------
__global__ __launch_bounds__(256) void k_mlp(
    const float* __restrict__ x,  const float* __restrict__ Wf, const float* __restrict__ bf,
    const float* __restrict__ W0, const float* __restrict__ b0,
    const float* __restrict__ W1, const float* __restrict__ b1)
{
    __shared__ float bufA[64 * 68];
    __shared__ float bufB[64 * 68];
    const int t  = threadIdx.x;
    const int tx = t & 15, ty = t >> 4;
    const int rowbase = blockIdx.x * 64;

    float* sX = bufA;
    float* sW = bufA + 32 * 68;

    float acc[4][4];
#pragma unroll
    for (int r = 0; r < 4; r++)
#pragma unroll
        for (int c = 0; c < 4; c++) acc[r][c] = 0.f;

    for (int kc = 0; kc < IN_DIM; kc += 32) {
        {
            int row = t >> 2, kq = (t & 3) * 8;
            const float* src = &x[(rowbase + row) * IN_DIM + kc + kq];
            float4 v0 = *(const float4*)(src);
            float4 v1 = *(const float4*)(src + 4);
            sX[(kq + 0) * 68 + row] = v0.x; sX[(kq + 1) * 68 + row] = v0.y;
            sX[(kq + 2) * 68 + row] = v0.z; sX[(kq + 3) * 68 + row] = v0.w;
            sX[(kq + 4) * 68 + row] = v1.x; sX[(kq + 5) * 68 + row] = v1.y;
            sX[(kq + 6) * 68 + row] = v1.z; sX[(kq + 7) * 68 + row] = v1.w;
            int k = t >> 3, cq = (t & 7) * 8;
            const float* ws = &Wf[(kc + k) * HID + cq];
            float4 w0 = *(const float4*)(ws);
            float4 w1 = *(const float4*)(ws + 4);
            *(float4*)&sW[k * 68 + cq]     = w0;
            *(float4*)&sW[k * 68 + cq + 4] = w1;
        }
        __syncthreads();
#pragma unroll 8
        for (int k = 0; k < 32; k++) {
            float a[4], w[4];
#pragma unroll
            for (int r = 0; r < 4; r++) a[r] = sX[k * 68 + ty + 16 * r];
#pragma unroll
            for (int c = 0; c < 4; c++) w[c] = sW[k * 68 + tx + 16 * c];
#pragma unroll
            for (int r = 0; r < 4; r++)
#pragma unroll
                for (int c = 0; c < 4; c++) acc[r][c] = fmaf(a[r], w[c], acc[r][c]);
        }
        __syncthreads();
    }
#pragma unroll
    for (int r = 0; r < 4; r++)
#pragma unroll
        for (int c = 0; c < 4; c++)
            bufB[(ty + 16 * r) * 68 + tx + 16 * c] = acc[r][c] + bf[tx + 16 * c];

    {
        int k = t >> 2, cq = (t & 3) * 16;
#pragma unroll
        for (int i = 0; i < 4; i++)
            *(float4*)&bufA[k * 68 + cq + 4 * i] = *(const float4*)&W0[k * HID + cq + 4 * i];
    }
    __syncthreads();

    float acc2[4][4];
#pragma unroll
    for (int r = 0; r < 4; r++)
#pragma unroll
        for (int c = 0; c < 4; c++) acc2[r][c] = 0.f;
#pragma unroll 4
    for (int k = 0; k < 64; k++) {
        float a[4], w[4];
#pragma unroll
        for (int r = 0; r < 4; r++) a[r] = bufB[(ty + 16 * r) * 68 + k];
#pragma unroll
        for (int c = 0; c < 4; c++) w[c] = bufA[k * 68 + tx + 16 * c];
#pragma unroll
        for (int r = 0; r < 4; r++)
#pragma unroll
            for (int c = 0; c < 4; c++) acc2[r][c] = fmaf(a[r], w[c], acc2[r][c]);
    }
    __syncthreads();
#pragma unroll
    for (int r = 0; r < 4; r++)
#pragma unroll
        for (int c = 0; c < 4; c++)
            bufA[(ty + 16 * r) * 68 + tx + 16 * c] =
                fmaxf(acc2[r][c] + b0[tx + 16 * c], 0.f);

    for (int cb = 0; cb < COMM; cb += 64) {
        {
            int k = t >> 2, cq = (t & 3) * 16;
#pragma unroll
            for (int i = 0; i < 4; i++)
                *(float4*)&bufB[k * 68 + cq + 4 * i] =
                    *(const float4*)&W1[k * COMM + cb + cq + 4 * i];
        }
        __syncthreads();
        float acc3[4][4];
#pragma unroll
        for (int r = 0; r < 4; r++)
#pragma unroll
            for (int c = 0; c < 4; c++) acc3[r][c] = 0.f;
#pragma unroll 4
        for (int k = 0; k < 64; k++) {
            float a[4], w[4];
#pragma unroll
            for (int r = 0; r < 4; r++) a[r] = bufA[(ty + 16 * r) * 68 + k];
#pragma unroll
            for (int c = 0; c < 4; c++) w[c] = bufB[k * 68 + tx + 16 * c];
#pragma unroll
            for (int r = 0; r < 4; r++)
#pragma unroll
                for (int c = 0; c < 4; c++) acc3[r][c] = fmaf(a[r], w[c], acc3[r][c]);
        }
#pragma unroll
        for (int r = 0; r < 4; r++)
#pragma unroll
            for (int c = 0; c < 4; c++)
                g_h3[(rowbase + ty + 16 * r) * COMM + cb + tx + 16 * c] =
                    fmaxf(acc3[r][c] + b1[cb + tx + 16 * c], 0.f);
        __syncthreads();
    }
}

// ---------- variational head: 16 rows / block, float4 LDS (same k-order FMA chain) ----------
__global__ __launch_bounds__(256) void k_head(
    const float* __restrict__ eps,
    const float* __restrict__ Wm, const float* __restrict__ bm,
    const float* __restrict__ Wv, const float* __restrict__ bv)
{
    __shared__ float  sH[16 * 256];
    __shared__ double sdk[8];
    const int t = threadIdx.x;
    const int rowbase = blockIdx.x * 16;

    if (t < 16) g_cnt[rowbase + t] = 0;

#pragma unroll
    for (int i = 0; i < 4; i++) {
        int f = i * 256 + t;
        int row = f >> 6, c4 = f & 63;
        *(float4*)&sH[row * 256 + c4 * 4] =
            *(const float4*)&g_h3[(rowbase + row) * COMM + c4 * 4];
    }
    __syncthreads();

    const int c = t;
    float ma[16], la[16];
#pragma unroll
    for (int r = 0; r < 16; r++) { ma[r] = 0.f; la[r] = 0.f; }
    for (int k = 0; k < COMM; k += 4) {
        float w0 = Wm[(k + 0) * COMM + c];
        float w1 = Wm[(k + 1) * COMM + c];
        float w2 = Wm[(k + 2) * COMM + c];
        float w3 = Wm[(k + 3) * COMM + c];
#pragma unroll
        for (int r = 0; r < 16; r++) {
            float4 h = *(const float4*)&sH[r * 256 + k];
            // identical accumulation order to the scalar loop: k, k+1, k+2, k+3
            ma[r] = fmaf(h.w, w3, fmaf(h.z, w2, fmaf(h.y, w1, fmaf(h.x, w0, ma[r]))));
        }
    }
    for (int k = 0; k < COMM; k += 4) {
        float w0 = Wv[(k + 0) * COMM + c];
        float w1 = Wv[(k + 1) * COMM + c];
        float w2 = Wv[(k + 2) * COMM + c];
        float w3 = Wv[(k + 3) * COMM + c];
#pragma unroll
        for (int r = 0; r < 16; r++) {
            float4 h = *(const float4*)&sH[r * 256 + k];
            la[r] = fmaf(h.w, w3, fmaf(h.z, w2, fmaf(h.y, w1, fmaf(h.x, w0, la[r]))));
        }
    }
    __syncthreads();

    const float bmc = bm[c], bvc = bv[c];
    double dk = 0.0;
#pragma unroll
    for (int r = 0; r < 16; r++) {
        float mu = __fadd_rn(ma[r], bmc);
        float lv = __fadd_rn(la[r], bvc);
        float e  = eps[(rowbase + r) * COMM + c];
        float s  = __fadd_rn(mu, __fmul_rn(e, expf(0.5f * lv)));
        g_sample[(rowbase + r) * COMM + c] = s;
        g_sbf[(rowbase + r) * COMM + c]    = __float2bfloat16_rn(s);
        dk += (double)(1.0f + lv - mu * mu - expf(lv));
        sH[r * 256 + c] = s * s;
    }
    __syncthreads();

    int w = t >> 5, lane = t & 31;
#pragma unroll
    for (int h = 0; h < 2; h++) {
        int r = w + 8 * h;
        float a = 0.f;
#pragma unroll
        for (int m = 0; m < 8; m++) a += sH[r * 256 + lane + 32 * m];
#pragma unroll
        for (int o = 16; o > 0; o >>= 1) a += __shfl_down_sync(0xffffffffu, a, o);
        if (lane == 0) g_sq[rowbase + r] = a;
    }

#pragma unroll
    for (int o = 16; o > 0; o >>= 1) dk += __shfl_down_sync(0xffffffffu, dk, o);
    if (lane == 0) sdk[w] = dk;
    __syncthreads();
    if (t == 0) {
        double v = 0.0;
#pragma unroll
        for (int i = 0; i < 8; i++) v += sdk[i];
        atomicAdd(&g_acc[1], v);
    }
}

// ---------- single-pass bf16 HMMA distance: 512 threads, 32x32 warp tiles ----------
// 256 blocks x 512 threads; 512 iterations (8 k-windows x 64 proto blocks).
__global__ __launch_bounds__(512) void k_dist_hmma()
{
    extern __shared__ __align__(16) char smDyn[];     // STAGES * STAGEB
    __shared__ float sRed[128 * 4];
    const int t = threadIdx.x;
    const int lane = t & 31, wid = t >> 5;
    const int wm = wid >> 2, wn = wid & 3;
    const int g = lane >> 2, tg = lane & 3;
    const int rowbase = blockIdx.x * 128;

    int   rowloc[4];
    float runmin[4], delta[4];
    const float pnm = sqrtf(__uint_as_float(g_pnmax_u));
#pragma unroll
    for (int i = 0; i < 4; i++) {
        int mt = i >> 1, h = i & 1;
        rowloc[i] = wm * 32 + mt * 16 + g + 8 * h;
        float sq = g_sq[rowbase + rowloc[i]];
        delta[i]  = 0.0082f * sqrtf(sq) * pnm + 2e-6f * sq + 1e-6f;
        runmin[i] = 3.4e38f;
    }

    // each thread copies ONE 16B chunk of A and ONE of B per stage
    const int cr = t >> 2, cc = t & 3;        // row 0-127, chunk 0-3
    const char* gA  = (const char*)g_sbf + (size_t)(rowbase + cr) * 512 + cc * 16;
    const char* gB0 = (const char*)g_pbf + (size_t)cr * 512 + cc * 16;
    const int smo = cr * ROWB + cc * 16;

    float acc[2][4][4];
#pragma unroll
    for (int mt = 0; mt < 2; mt++)
#pragma unroll
        for (int nt = 0; nt < 4; nt++)
#pragma unroll
            for (int q = 0; q < 4; q++) acc[mt][nt][q] = 0.f;

    // stage issuer: gmem -> smem ring buffer, one commit group per stage
#define ISSUE_STAGE(st) do {                                                         \
        int w2 = (st) & 7, nb2 = (st) >> 3;                                          \
        const char* a2 = gA + w2 * 64;                                               \
        const char* b2 = gB0 + (size_t)nb2 * 128 * 512 + w2 * 64;                    \
        char* buf = smDyn + ((st) & (STAGES - 1)) * STAGEB;                          \
        unsigned sa = (unsigned)__cvta_generic_to_shared(buf + smo);                 \
        unsigned sb = (unsigned)__cvta_generic_to_shared(buf + TILEB + smo);         \
        asm volatile("cp.async.cg.shared.global [%0], [%1], 16;\n"                   \
                     :: "r"(sa), "l"(a2));                                           \
        asm volatile("cp.async.cg.shared.global [%0], [%1], 16;\n"                   \
                     :: "r"(sb), "l"(b2));                                           \
        asm volatile("cp.async.commit_group;\n");                                    \
    } while (0)

    ISSUE_STAGE(0);
    ISSUE_STAGE(1);
    ISSUE_STAGE(2);

#pragma unroll 1
    for (int it = 0; it < 512; ++it) {
        const int w8 = it & 7, nb = it >> 3;
        // wait until stage `it` has landed (exact tail counts)
        if (it < 510)       asm volatile("cp.async.wait_group 2;\n" ::: "memory");
        else if (it == 510) asm volatile("cp.async.wait_group 1;\n" ::: "memory");
        else                asm volatile("cp.async.wait_group 0;\n" ::: "memory");
        __syncthreads();

        char* bufp = smDyn + (it & (STAGES - 1)) * STAGEB;

        // refill: stage it+3 overwrites the buffer consumed in iteration it-1
        if (it + 3 < 512) ISSUE_STAGE(it + 3);

        // two K=16 steps per buffer
#pragma unroll
        for (int ks = 0; ks < 2; ks++) {
            unsigned a[2][4], bfr[4][2];
#pragma unroll
            for (int mt = 0; mt < 2; mt++) {
                int r  = wm * 32 + mt * 16 + (lane & 15);
                int ch = ks * 2 + (lane >> 4);
                unsigned ad = (unsigned)__cvta_generic_to_shared(bufp + r * ROWB + ch * 16);
                asm volatile("ldmatrix.sync.aligned.m8n8.x4.shared.b16 {%0,%1,%2,%3},[%4];"
                    : "=r"(a[mt][0]), "=r"(a[mt][1]), "=r"(a[mt][2]), "=r"(a[mt][3]) : "r"(ad));
            }
            // B fragments: one x4 per nt-pair (matrices: nt even ch0, nt even ch1,
            // nt odd ch0, nt odd ch1 selected by lane groups of 8)
#pragma unroll
            for (int q = 0; q < 2; q++) {
                int n  = wn * 32 + q * 16 + ((lane >> 4) << 3) + (lane & 7);
                int ch = ks * 2 + ((lane >> 3) & 1);
                unsigned ad = (unsigned)__cvta_generic_to_shared(bufp + TILEB + n * ROWB + ch * 16);
                asm volatile("ldmatrix.sync.aligned.m8n8.x4.shared.b16 {%0,%1,%2,%3},[%4];"
                    : "=r"(bfr[2 * q][0]), "=r"(bfr[2 * q][1]),
                      "=r"(bfr[2 * q + 1][0]), "=r"(bfr[2 * q + 1][1]) : "r"(ad));
            }
#pragma unroll
            for (int mt = 0; mt < 2; mt++)
#pragma unroll
                for (int nt = 0; nt < 4; nt++)
                    asm volatile(
                        "mma.sync.aligned.m16n8k16.row.col.f32.bf16.bf16.f32 "
                        "{%0,%1,%2,%3},{%4,%5,%6,%7},{%8,%9},{%0,%1,%2,%3};"
                        : "+f"(acc[mt][nt][0]), "+f"(acc[mt][nt][1]),
                          "+f"(acc[mt][nt][2]), "+f"(acc[mt][nt][3])
                        : "r"(a[mt][0]), "r"(a[mt][1]), "r"(a[mt][2]), "r"(a[mt][3]),
                          "r"(bfr[nt][0]), "r"(bfr[nt][1]));
        }

        if (w8 == 7) {
            const int jbase = nb * 128;
            float tmin[4];
#pragma unroll
            for (int i = 0; i < 4; i++) tmin[i] = 3.4e38f;
#pragma unroll
            for (int nt = 0; nt < 4; nt++) {
                int j0 = jbase + wn * 32 + nt * 8 + 2 * tg;
                float pn0 = __ldg(&g_pn[j0]), pn1 = __ldg(&g_pn[j0 + 1]);
#pragma unroll
                for (int mt = 0; mt < 2; mt++) {
                    acc[mt][nt][0] = fmaf(-2.f, acc[mt][nt][0], pn0);
                    acc[mt][nt][1] = fmaf(-2.f, acc[mt][nt][1], pn1);
                    acc[mt][nt][2] = fmaf(-2.f, acc[mt][nt][2], pn0);
                    acc[mt][nt][3] = fmaf(-2.f, acc[mt][nt][3], pn1);
                    tmin[mt * 2]     = fminf(tmin[mt * 2],
                                             fminf(acc[mt][nt][0], acc[mt][nt][1]));
                    tmin[mt * 2 + 1] = fminf(tmin[mt * 2 + 1],
                                             fminf(acc[mt][nt][2], acc[mt][nt][3]));
                }
            }
#pragma unroll
            for (int i = 0; i < 4; i++) {
                tmin[i] = fminf(tmin[i], __shfl_xor_sync(0xffffffffu, tmin[i], 1));
                tmin[i] = fminf(tmin[i], __shfl_xor_sync(0xffffffffu, tmin[i], 2));
            }
            if (tg == 0) {
#pragma unroll
                for (int i = 0; i < 4; i++) sRed[rowloc[i] * 4 + wn] = tmin[i];
            }
            __syncthreads();
            float th[4];
#pragma unroll
            for (int i = 0; i < 4; i++) {
                float tm = fminf(fminf(sRed[rowloc[i] * 4 + 0], sRed[rowloc[i] * 4 + 1]),
                                 fminf(sRed[rowloc[i] * 4 + 2], sRed[rowloc[i] * 4 + 3]));
                float m = fminf(runmin[i], tm);
                th[i] = m + delta[i];
                runmin[i] = m;
            }
#pragma unroll
            for (int nt = 0; nt < 4; nt++) {
                int j0 = jbase + wn * 32 + nt * 8 + 2 * tg;
#pragma unroll
                for (int mt = 0; mt < 2; mt++) {
                    int i0 = mt * 2, i1 = mt * 2 + 1;
                    int row0 = rowbase + rowloc[i0];
                    int row1 = rowbase + rowloc[i1];
                    if (acc[mt][nt][0] <= th[i0]) { int sl = atomicAdd(&g_cnt[row0], 1); if (sl < MAXC) g_cand[row0 * MAXC + sl] = j0; }
                    if (acc[mt][nt][1] <= th[i0]) { int sl = atomicAdd(&g_cnt[row0], 1); if (sl < MAXC) g_cand[row0 * MAXC + sl] = j0 + 1; }
                    if (acc[mt][nt][2] <= th[i1]) { int sl = atomicAdd(&g_cnt[row1], 1); if (sl < MAXC) g_cand[row1 * MAXC + sl] = j0; }
                    if (acc[mt][nt][3] <= th[i1]) { int sl = atomicAdd(&g_cnt[row1], 1); if (sl < MAXC) g_cand[row1 * MAXC + sl] = j0 + 1; }
                    acc[mt][nt][0] = 0.f; acc[mt][nt][1] = 0.f;
                    acc[mt][nt][2] = 0.f; acc[mt][nt][3] = 0.f;
                }
            }
            __syncthreads();
        }
    }
#undef ISSUE_STAGE
}

// ---------- exact fp32 rescue: resolve argmin among candidates ----------
__global__ __launch_bounds__(256) void k_resolve(const float* __restrict__ protos)
{
    const int wid = threadIdx.x >> 5, lane = threadIdx.x & 31;
    const int row = blockIdx.x * 8 + wid;
    const int cnt = g_cnt[row];
    if (cnt == 1) {
        if (lane == 0) g_idx[row] = g_cand[row * MAXC];
        return;
    }
    const float* s = &g_sample[(size_t)row * COMM];
    const float sq = g_sq[row];
    float bd = 3.4e38f; int bj = 0x7fffffff;
    if (cnt >= 2 && cnt <= MAXC) {
        for (int c = lane; c < cnt; c += 32) {
            int j = g_cand[row * MAXC + c];
            const float* p = &protos[(size_t)j * COMM];
            float acc = 0.f;
            for (int k = 0; k < COMM; k++) acc = fmaf(s[k], p[k], acc);
            float t1 = __fadd_rn(sq, g_pn[j]);
            float d  = __fadd_rn(t1, -__fmul_rn(2.0f, acc));
            if (d < bd || (d == bd && j < bj)) { bd = d; bj = j; }
        }
    } else {   // cnt == 0 (shouldn't happen) or overflow: exact full scan
        for (int j = lane; j < KP; j += 32) {
            const float* p = &protos[(size_t)j * COMM];
            float acc = 0.f;
            for (int k = 0; k < COMM; k++) acc = fmaf(s[k], p[k], acc);
            float t1 = __fadd_rn(sq, g_pn[j]);
            float d  = __fadd_rn(t1, -__fmul_rn(2.0f, acc));
            if (d < bd) { bd = d; bj = j; }
        }
    }
#pragma unroll
    for (int o = 16; o > 0; o >>= 1) {
        float od = __shfl_xor_sync(0xffffffffu, bd, o);
        int   oj = __shfl_xor_sync(0xffffffffu, bj, o);
        if (od < bd || (od == bd && oj < bj)) { bd = od; bj = oj; }
    }
    if (lane == 0) g_idx[row] = bj;
}

// ---------- gather q, write q_st, accumulate (q-s)^2 ----------
__global__ __launch_bounds__(256) void k_final(const float* __restrict__ protos,
                                               float* __restrict__ out)
{
    __shared__ double sdk[8];
    const int t = threadIdx.x;
    const int rowbase = blockIdx.x * 32;
    double s2 = 0.0;
    for (int r = 0; r < 32; r++) {
        int row = rowbase + r;
        int idx = g_idx[row];
        float q    = protos[idx * COMM + t];
        float s    = g_sample[row * COMM + t];
        float diff = __fsub_rn(q, s);
        out[row * COMM + t] = __fadd_rn(s, diff);
        s2 += (double)diff * (double)diff;
    }
    int w = t >> 5, lane = t & 31;
#pragma unroll
    for (int o = 16; o > 0; o >>= 1) s2 += __shfl_down_sync(0xffffffffu, s2, o);
    if (lane == 0) sdk[w] = s2;
    __syncthreads();
    if (t == 0) {
        double v = 0.0;
#pragma unroll
        for (int i = 0; i < 8; i++) v += sdk[i];
        atomicAdd(&g_acc[0], v);
    }
}

// ---------- scalars ----------
__global__ void k_scalar(float* __restrict__ out, int out_size)
{
    double m   = g_acc[0] / ((double)B_ROWS * (double)COMM);
    double kld = -0.5 * g_acc[1] / (double)B_ROWS;
    double total = kld + 1.25 * m;
    out[out_size - 2] = (float)total;
    out[out_size - 1] = (float)kld;
}

extern "C" void kernel_launch(void* const* d_in, const int* in_sizes, int n_in,
                              void* d_out, int out_size)
{
    const float* x      = (const float*)d_in[0];
    const float* eps    = (const float*)d_in[1];
    const float* W_feat = (const float*)d_in[2];
    const float* b_feat = (const float*)d_in[3];
    const float* W0     = (const float*)d_in[4];
    const float* b0     = (const float*)d_in[5];
    const float* W1     = (const float*)d_in[6];
    const float* b1     = (const float*)d_in[7];
    const float* W_mu   = (const float*)d_in[8];
    const float* b_mu   = (const float*)d_in[9];
    const float* W_var  = (const float*)d_in[10];
    const float* b_var  = (const float*)d_in[11];
    const float* protos = (const float*)d_in[12];
    float* out = (float*)d_out;

    cudaFuncSetAttribute(k_dist_hmma, cudaFuncAttributeMaxDynamicSharedMemorySize, DSMEM);

    k_pn<<<KP / 8, 256>>>(protos);
    k_mlp<<<B_ROWS / 64, 256>>>(x, W_feat, b_feat, W0, b0, W1, b1);
    k_head<<<B_ROWS / 16, 256>>>(eps, W_mu, b_mu, W_var, b_var);
    k_dist_hmma<<<B_ROWS / 128, 512, DSMEM>>>();
    k_resolve<<<B_ROWS / 8, 256>>>(protos);
    k_final<<<B_ROWS / 32, 256>>>(protos, out);
    k_scalar<<<1, 1>>>(out, out_size);
}

// round 17
// speedup vs baseline: 1.3039x; 1.0178x over previous
#include <cuda_runtime.h>
#include <cuda_bf16.h>
#include <math.h>
#include <stdint.h>

#define B_ROWS 32768
#define IN_DIM 1024
#define HID    64
#define COMM   256
#define KP     8192
#define MAXC   48

#define ROWB   80      // dist smem row stride: 64B data (K=32 bf16) + 16B pad
#define TILEB  10240   // 128 rows * 80B
#define STAGEB (2 * TILEB)      // A tile + B tile per stage
#define STAGES 2
#define DSMEM  (STAGES * STAGEB)   // 40960 dynamic smem -> 2 CTAs/SM

// ---------- scratch (no runtime allocation allowed) ----------
__device__ float  g_h3[B_ROWS * COMM];
__device__ float  g_sample[B_ROWS * COMM];
__device__ __nv_bfloat16 g_sbf[B_ROWS * COMM];
__device__ __nv_bfloat16 g_pbf[KP * COMM];
__device__ float  g_sq[B_ROWS];
__device__ float  g_pn[KP];
__device__ unsigned int g_pnmax_u;   // monotone: atomicMax is idempotent across replays
__device__ int    g_cnt[B_ROWS];
__device__ int    g_cand[B_ROWS * MAXC];
__device__ int    g_idx[B_ROWS];
__device__ double g_acc[2];

// ---------- proto squared norms + bf16 conversion (+ accumulator zeroing) ----------
__global__ void k_pn(const float* __restrict__ protos) {
    if (blockIdx.x == 0 && threadIdx.x == 0) { g_acc[0] = 0.0; g_acc[1] = 0.0; }
    int row  = blockIdx.x * 8 + (threadIdx.x >> 5);
    int lane = threadIdx.x & 31;
    float a = 0.f;
#pragma unroll
    for (int m = 0; m < 8; m++) {
        float v = protos[row * COMM + lane + 32 * m];
        g_pbf[row * COMM + lane + 32 * m] = __float2bfloat16_rn(v);
        a = fmaf(v, v, a);
    }
#pragma unroll
    for (int o = 16; o > 0; o >>= 1) a += __shfl_down_sync(0xffffffffu, a, o);
    if (lane == 0) {
        g_pn[row] = a;
        atomicMax(&g_pnmax_u, __float_as_uint(a));
    }
}

// ---------- fused MLP (unchanged, validated) ----------
__global__ __launch_bounds__(256) void k_mlp(
    const float* __restrict__ x,  const float* __restrict__ Wf, const float* __restrict__ bf,
    const float* __restrict__ W0, const float* __restrict__ b0,
    const float* __restrict__ W1, const float* __restrict__ b1)
{
    __shared__ float bufA[64 * 68];
    __shared__ float bufB[64 * 68];
    const int t  = threadIdx.x;
    const int tx = t & 15, ty = t >> 4;
    const int rowbase = blockIdx.x * 64;

    float* sX = bufA;
    float* sW = bufA + 32 * 68;

    float acc[4][4];
#pragma unroll
    for (int r = 0; r < 4; r++)
#pragma unroll
        for (int c = 0; c < 4; c++) acc[r][c] = 0.f;

    for (int kc = 0; kc < IN_DIM; kc += 32) {
        {
            int row = t >> 2, kq = (t & 3) * 8;
            const float* src = &x[(rowbase + row) * IN_DIM + kc + kq];
            float4 v0 = *(const float4*)(src);
            float4 v1 = *(const float4*)(src + 4);
            sX[(kq + 0) * 68 + row] = v0.x; sX[(kq + 1) * 68 + row] = v0.y;
            sX[(kq + 2) * 68 + row] = v0.z; sX[(kq + 3) * 68 + row] = v0.w;
            sX[(kq + 4) * 68 + row] = v1.x; sX[(kq + 5) * 68 + row] = v1.y;
            sX[(kq + 6) * 68 + row] = v1.z; sX[(kq + 7) * 68 + row] = v1.w;
            int k = t >> 3, cq = (t & 7) * 8;
            const float* ws = &Wf[(kc + k) * HID + cq];
            float4 w0 = *(const float4*)(ws);
            float4 w1 = *(const float4*)(ws + 4);
            *(float4*)&sW[k * 68 + cq]     = w0;
            *(float4*)&sW[k * 68 + cq + 4] = w1;
        }
        __syncthreads();
#pragma unroll 8
        for (int k = 0; k < 32; k++) {
            float a[4], w[4];
#pragma unroll
            for (int r = 0; r < 4; r++) a[r] = sX[k * 68 + ty + 16 * r];
#pragma unroll
            for (int c = 0; c < 4; c++) w[c] = sW[k * 68 + tx + 16 * c];
#pragma unroll
            for (int r = 0; r < 4; r++)
#pragma unroll
                for (int c = 0; c < 4; c++) acc[r][c] = fmaf(a[r], w[c], acc[r][c]);
        }
        __syncthreads();
    }
#pragma unroll
    for (int r = 0; r < 4; r++)
#pragma unroll
        for (int c = 0; c < 4; c++)
            bufB[(ty + 16 * r) * 68 + tx + 16 * c] = acc[r][c] + bf[tx + 16 * c];

    {
        int k = t >> 2, cq = (t & 3) * 16;
#pragma unroll
        for (int i = 0; i < 4; i++)
            *(float4*)&bufA[k * 68 + cq + 4 * i] = *(const float4*)&W0[k * HID + cq + 4 * i];
    }
    __syncthreads();

    float acc2[4][4];
#pragma unroll
    for (int r = 0; r < 4; r++)
#pragma unroll
        for (int c = 0; c < 4; c++) acc2[r][c] = 0.f;
#pragma unroll 4
    for (int k = 0; k < 64; k++) {
        float a[4], w[4];
#pragma unroll
        for (int r = 0; r < 4; r++) a[r] = bufB[(ty + 16 * r) * 68 + k];
#pragma unroll
        for (int c = 0; c < 4; c++) w[c] = bufA[k * 68 + tx + 16 * c];
#pragma unroll
        for (int r = 0; r < 4; r++)
#pragma unroll
            for (int c = 0; c < 4; c++) acc2[r][c] = fmaf(a[r], w[c], acc2[r][c]);
    }
    __syncthreads();
#pragma unroll
    for (int r = 0; r < 4; r++)
#pragma unroll
        for (int c = 0; c < 4; c++)
            bufA[(ty + 16 * r) * 68 + tx + 16 * c] =
                fmaxf(acc2[r][c] + b0[tx + 16 * c], 0.f);

    for (int cb = 0; cb < COMM; cb += 64) {
        {
            int k = t >> 2, cq = (t & 3) * 16;
#pragma unroll
            for (int i = 0; i < 4; i++)
                *(float4*)&bufB[k * 68 + cq + 4 * i] =
                    *(const float4*)&W1[k * COMM + cb + cq + 4 * i];
        }
        __syncthreads();
        float acc3[4][4];
#pragma unroll
        for (int r = 0; r < 4; r++)
#pragma unroll
            for (int c = 0; c < 4; c++) acc3[r][c] = 0.f;
#pragma unroll 4
        for (int k = 0; k < 64; k++) {
            float a[4], w[4];
#pragma unroll
            for (int r = 0; r < 4; r++) a[r] = bufA[(ty + 16 * r) * 68 + k];
#pragma unroll
            for (int c = 0; c < 4; c++) w[c] = bufB[k * 68 + tx + 16 * c];
#pragma unroll
            for (int r = 0; r < 4; r++)
#pragma unroll
                for (int c = 0; c < 4; c++) acc3[r][c] = fmaf(a[r], w[c], acc3[r][c]);
        }
#pragma unroll
        for (int r = 0; r < 4; r++)
#pragma unroll
            for (int c = 0; c < 4; c++)
                g_h3[(rowbase + ty + 16 * r) * COMM + cb + tx + 16 * c] =
                    fmaxf(acc3[r][c] + b1[cb + tx + 16 * c], 0.f);
        __syncthreads();
    }
}

// ---------- variational head: 16 rows / block, float4 LDS (same k-order FMA chain) ----------
__global__ __launch_bounds__(256) void k_head(
    const float* __restrict__ eps,
    const float* __restrict__ Wm, const float* __restrict__ bm,
    const float* __restrict__ Wv, const float* __restrict__ bv)
{
    __shared__ float  sH[16 * 256];
    __shared__ double sdk[8];
    const int t = threadIdx.x;
    const int rowbase = blockIdx.x * 16;

    if (t < 16) g_cnt[rowbase + t] = 0;

#pragma unroll
    for (int i = 0; i < 4; i++) {
        int f = i * 256 + t;
        int row = f >> 6, c4 = f & 63;
        *(float4*)&sH[row * 256 + c4 * 4] =
            *(const float4*)&g_h3[(rowbase + row) * COMM + c4 * 4];
    }
    __syncthreads();

    const int c = t;
    float ma[16], la[16];
#pragma unroll
    for (int r = 0; r < 16; r++) { ma[r] = 0.f; la[r] = 0.f; }
    for (int k = 0; k < COMM; k += 4) {
        float w0 = Wm[(k + 0) * COMM + c];
        float w1 = Wm[(k + 1) * COMM + c];
        float w2 = Wm[(k + 2) * COMM + c];
        float w3 = Wm[(k + 3) * COMM + c];
#pragma unroll
        for (int r = 0; r < 16; r++) {
            float4 h = *(const float4*)&sH[r * 256 + k];
            ma[r] = fmaf(h.w, w3, fmaf(h.z, w2, fmaf(h.y, w1, fmaf(h.x, w0, ma[r]))));
        }
    }
    for (int k = 0; k < COMM; k += 4) {
        float w0 = Wv[(k + 0) * COMM + c];
        float w1 = Wv[(k + 1) * COMM + c];
        float w2 = Wv[(k + 2) * COMM + c];
        float w3 = Wv[(k + 3) * COMM + c];
#pragma unroll
        for (int r = 0; r < 16; r++) {
            float4 h = *(const float4*)&sH[r * 256 + k];
            la[r] = fmaf(h.w, w3, fmaf(h.z, w2, fmaf(h.y, w1, fmaf(h.x, w0, la[r]))));
        }
    }
    __syncthreads();

    const float bmc = bm[c], bvc = bv[c];
    double dk = 0.0;
#pragma unroll
    for (int r = 0; r < 16; r++) {
        float mu = __fadd_rn(ma[r], bmc);
        float lv = __fadd_rn(la[r], bvc);
        float e  = eps[(rowbase + r) * COMM + c];
        float s  = __fadd_rn(mu, __fmul_rn(e, expf(0.5f * lv)));
        g_sample[(rowbase + r) * COMM + c] = s;
        g_sbf[(rowbase + r) * COMM + c]    = __float2bfloat16_rn(s);
        dk += (double)(1.0f + lv - mu * mu - expf(lv));
        sH[r * 256 + c] = s * s;
    }
    __syncthreads();

    int w = t >> 5, lane = t & 31;
#pragma unroll
    for (int h = 0; h < 2; h++) {
        int r = w + 8 * h;
        float a = 0.f;
#pragma unroll
        for (int m = 0; m < 8; m++) a += sH[r * 256 + lane + 32 * m];
#pragma unroll
        for (int o = 16; o > 0; o >>= 1) a += __shfl_down_sync(0xffffffffu, a, o);
        if (lane == 0) g_sq[rowbase + r] = a;
    }

#pragma unroll
    for (int o = 16; o > 0; o >>= 1) dk += __shfl_down_sync(0xffffffffu, dk, o);
    if (lane == 0) sdk[w] = dk;
    __syncthreads();
    if (t == 0) {
        double v = 0.0;
#pragma unroll
        for (int i = 0; i < 8; i++) v += sdk[i];
        atomicAdd(&g_acc[1], v);
    }
}

// ---------- single-pass bf16 HMMA distance: 512 thr, 32x32 warp tiles, 2 CTAs/SM ----------
// 256 blocks x 512 threads; 512 iterations (8 k-windows x 64 proto blocks).
// 2-stage cp.async ring: wait stage it, consume, barrier, refill it+2.
__global__ __launch_bounds__(512, 2) void k_dist_hmma()
{
    extern __shared__ __align__(16) char smDyn[];     // STAGES * STAGEB
    __shared__ float sRed[128 * 4];
    const int t = threadIdx.x;
    const int lane = t & 31, wid = t >> 5;
    const int wm = wid >> 2, wn = wid & 3;
    const int g = lane >> 2, tg = lane & 3;
    const int rowbase = blockIdx.x * 128;

    int   rowloc[4];
    float runmin[4], delta[4];
    const float pnm = sqrtf(__uint_as_float(g_pnmax_u));
#pragma unroll
    for (int i = 0; i < 4; i++) {
        int mt = i >> 1, h = i & 1;
        rowloc[i] = wm * 32 + mt * 16 + g + 8 * h;
        float sq = g_sq[rowbase + rowloc[i]];
        delta[i]  = 0.0082f * sqrtf(sq) * pnm + 2e-6f * sq + 1e-6f;
        runmin[i] = 3.4e38f;
    }

    // each thread copies ONE 16B chunk of A and ONE of B per stage
    const int cr = t >> 2, cc = t & 3;        // row 0-127, chunk 0-3
    const char* gA  = (const char*)g_sbf + (size_t)(rowbase + cr) * 512 + cc * 16;
    const char* gB0 = (const char*)g_pbf + (size_t)cr * 512 + cc * 16;
    const int smo = cr * ROWB + cc * 16;

    float acc[2][4][4];
#pragma unroll
    for (int mt = 0; mt < 2; mt++)
#pragma unroll
        for (int nt = 0; nt < 4; nt++)
#pragma unroll
            for (int q = 0; q < 4; q++) acc[mt][nt][q] = 0.f;

    // stage issuer: gmem -> smem ring buffer, one commit group per stage
#define ISSUE_STAGE(st) do {                                                         \
        int w2 = (st) & 7, nb2 = (st) >> 3;                                          \
        const char* a2 = gA + w2 * 64;                                               \
        const char* b2 = gB0 + (size_t)nb2 * 128 * 512 + w2 * 64;                    \
        char* buf = smDyn + ((st) & (STAGES - 1)) * STAGEB;                          \
        unsigned sa = (unsigned)__cvta_generic_to_shared(buf + smo);                 \
        unsigned sb = (unsigned)__cvta_generic_to_shared(buf + TILEB + smo);         \
        asm volatile("cp.async.cg.shared.global [%0], [%1], 16;\n"                   \
                     :: "r"(sa), "l"(a2));                                           \
        asm volatile("cp.async.cg.shared.global [%0], [%1], 16;\n"                   \
                     :: "r"(sb), "l"(b2));                                           \
        asm volatile("cp.async.commit_group;\n");                                    \
    } while (0)

    ISSUE_STAGE(0);
    ISSUE_STAGE(1);

#pragma unroll 1
    for (int it = 0; it < 512; ++it) {
        const int w8 = it & 7, nb = it >> 3;
        // wait until stage `it` has landed (pending: it+1, except at tail)
        if (it < 511) asm volatile("cp.async.wait_group 1;\n" ::: "memory");
        else          asm volatile("cp.async.wait_group 0;\n" ::: "memory");
        __syncthreads();

        char* bufp = smDyn + (it & (STAGES - 1)) * STAGEB;

        // two K=16 steps per buffer
#pragma unroll
        for (int ks = 0; ks < 2; ks++) {
            unsigned a[2][4], bfr[4][2];
#pragma unroll
            for (int mt = 0; mt < 2; mt++) {
                int r  = wm * 32 + mt * 16 + (lane & 15);
                int ch = ks * 2 + (lane >> 4);
                unsigned ad = (unsigned)__cvta_generic_to_shared(bufp + r * ROWB + ch * 16);
                asm volatile("ldmatrix.sync.aligned.m8n8.x4.shared.b16 {%0,%1,%2,%3},[%4];"
                    : "=r"(a[mt][0]), "=r"(a[mt][1]), "=r"(a[mt][2]), "=r"(a[mt][3]) : "r"(ad));
            }
            // B fragments: one x4 per nt-pair
#pragma unroll
            for (int q = 0; q < 2; q++) {
                int n  = wn * 32 + q * 16 + ((lane >> 4) << 3) + (lane & 7);
                int ch = ks * 2 + ((lane >> 3) & 1);
                unsigned ad = (unsigned)__cvta_generic_to_shared(bufp + TILEB + n * ROWB + ch * 16);
                asm volatile("ldmatrix.sync.aligned.m8n8.x4.shared.b16 {%0,%1,%2,%3},[%4];"
                    : "=r"(bfr[2 * q][0]), "=r"(bfr[2 * q][1]),
                      "=r"(bfr[2 * q + 1][0]), "=r"(bfr[2 * q + 1][1]) : "r"(ad));
            }
#pragma unroll
            for (int mt = 0; mt < 2; mt++)
#pragma unroll
                for (int nt = 0; nt < 4; nt++)
                    asm volatile(
                        "mma.sync.aligned.m16n8k16.row.col.f32.bf16.bf16.f32 "
                        "{%0,%1,%2,%3},{%4,%5,%6,%7},{%8,%9},{%0,%1,%2,%3};"
                        : "+f"(acc[mt][nt][0]), "+f"(acc[mt][nt][1]),
                          "+f"(acc[mt][nt][2]), "+f"(acc[mt][nt][3])
                        : "r"(a[mt][0]), "r"(a[mt][1]), "r"(a[mt][2]), "r"(a[mt][3]),
                          "r"(bfr[nt][0]), "r"(bfr[nt][1]));
        }

        // all warps done reading buffer `it`; safe to refill it with stage it+2.
        __syncthreads();
        if (it + 2 < 512) ISSUE_STAGE(it + 2);

        if (w8 == 7) {
            const int jbase = nb * 128;
            float tmin[4];
#pragma unroll
            for (int i = 0; i < 4; i++) tmin[i] = 3.4e38f;
#pragma unroll
            for (int nt = 0; nt < 4; nt++) {
                int j0 = jbase + wn * 32 + nt * 8 + 2 * tg;
                float pn0 = __ldg(&g_pn[j0]), pn1 = __ldg(&g_pn[j0 + 1]);
#pragma unroll
                for (int mt = 0; mt < 2; mt++) {
                    acc[mt][nt][0] = fmaf(-2.f, acc[mt][nt][0], pn0);
                    acc[mt][nt][1] = fmaf(-2.f, acc[mt][nt][1], pn1);
                    acc[mt][nt][2] = fmaf(-2.f, acc[mt][nt][2], pn0);
                    acc[mt][nt][3] = fmaf(-2.f, acc[mt][nt][3], pn1);
                    tmin[mt * 2]     = fminf(tmin[mt * 2],
                                             fminf(acc[mt][nt][0], acc[mt][nt][1]));
                    tmin[mt * 2 + 1] = fminf(tmin[mt * 2 + 1],
                                             fminf(acc[mt][nt][2], acc[mt][nt][3]));
                }
            }
#pragma unroll
            for (int i = 0; i < 4; i++) {
                tmin[i] = fminf(tmin[i], __shfl_xor_sync(0xffffffffu, tmin[i], 1));
                tmin[i] = fminf(tmin[i], __shfl_xor_sync(0xffffffffu, tmin[i], 2));
            }
            if (tg == 0) {
#pragma unroll
                for (int i = 0; i < 4; i++) sRed[rowloc[i] * 4 + wn] = tmin[i];
            }
            __syncthreads();
            float th[4];
#pragma unroll
            for (int i = 0; i < 4; i++) {
                float tm = fminf(fminf(sRed[rowloc[i] * 4 + 0], sRed[rowloc[i] * 4 + 1]),
                                 fminf(sRed[rowloc[i] * 4 + 2], sRed[rowloc[i] * 4 + 3]));
                float m = fminf(runmin[i], tm);
                th[i] = m + delta[i];
                runmin[i] = m;
            }
#pragma unroll
            for (int nt = 0; nt < 4; nt++) {
                int j0 = jbase + wn * 32 + nt * 8 + 2 * tg;
#pragma unroll
                for (int mt = 0; mt < 2; mt++) {
                    int i0 = mt * 2, i1 = mt * 2 + 1;
                    int row0 = rowbase + rowloc[i0];
                    int row1 = rowbase + rowloc[i1];
                    if (acc[mt][nt][0] <= th[i0]) { int sl = atomicAdd(&g_cnt[row0], 1); if (sl < MAXC) g_cand[row0 * MAXC + sl] = j0; }
                    if (acc[mt][nt][1] <= th[i0]) { int sl = atomicAdd(&g_cnt[row0], 1); if (sl < MAXC) g_cand[row0 * MAXC + sl] = j0 + 1; }
                    if (acc[mt][nt][2] <= th[i1]) { int sl = atomicAdd(&g_cnt[row1], 1); if (sl < MAXC) g_cand[row1 * MAXC + sl] = j0; }
                    if (acc[mt][nt][3] <= th[i1]) { int sl = atomicAdd(&g_cnt[row1], 1); if (sl < MAXC) g_cand[row1 * MAXC + sl] = j0 + 1; }
                    acc[mt][nt][0] = 0.f; acc[mt][nt][1] = 0.f;
                    acc[mt][nt][2] = 0.f; acc[mt][nt][3] = 0.f;
                }
            }
            __syncthreads();
        }
    }
#undef ISSUE_STAGE
}

// ---------- exact fp32 rescue: resolve argmin among candidates ----------
__global__ __launch_bounds__(256) void k_resolve(const float* __restrict__ protos)
{
    const int wid = threadIdx.x >> 5, lane = threadIdx.x & 31;
    const int row = blockIdx.x * 8 + wid;
    const int cnt = g_cnt[row];
    if (cnt == 1) {
        if (lane == 0) g_idx[row] = g_cand[row * MAXC];
        return;
    }
    const float* s = &g_sample[(size_t)row * COMM];
    const float sq = g_sq[row];
    float bd = 3.4e38f; int bj = 0x7fffffff;
    if (cnt >= 2 && cnt <= MAXC) {
        for (int c = lane; c < cnt; c += 32) {
            int j = g_cand[row * MAXC + c];
            const float* p = &protos[(size_t)j * COMM];
            float acc = 0.f;
            for (int k = 0; k < COMM; k++) acc = fmaf(s[k], p[k], acc);
            float t1 = __fadd_rn(sq, g_pn[j]);
            float d  = __fadd_rn(t1, -__fmul_rn(2.0f, acc));
            if (d < bd || (d == bd && j < bj)) { bd = d; bj = j; }
        }
    } else {   // cnt == 0 (shouldn't happen) or overflow: exact full scan
        for (int j = lane; j < KP; j += 32) {
            const float* p = &protos[(size_t)j * COMM];
            float acc = 0.f;
            for (int k = 0; k < COMM; k++) acc = fmaf(s[k], p[k], acc);
            float t1 = __fadd_rn(sq, g_pn[j]);
            float d  = __fadd_rn(t1, -__fmul_rn(2.0f, acc));
            if (d < bd) { bd = d; bj = j; }
        }
    }
#pragma unroll
    for (int o = 16; o > 0; o >>= 1) {
        float od = __shfl_xor_sync(0xffffffffu, bd, o);
        int   oj = __shfl_xor_sync(0xffffffffu, bj, o);
        if (od < bd || (od == bd && oj < bj)) { bd = od; bj = oj; }
    }
    if (lane == 0) g_idx[row] = bj;
}

// ---------- gather q, write q_st, accumulate (q-s)^2 ----------
__global__ __launch_bounds__(256) void k_final(const float* __restrict__ protos,
                                               float* __restrict__ out)
{
    __shared__ double sdk[8];
    const int t = threadIdx.x;
    const int rowbase = blockIdx.x * 32;
    double s2 = 0.0;
    for (int r = 0; r < 32; r++) {
        int row = rowbase + r;
        int idx = g_idx[row];
        float q    = protos[idx * COMM + t];
        float s    = g_sample[row * COMM + t];
        float diff = __fsub_rn(q, s);
        out[row * COMM + t] = __fadd_rn(s, diff);
        s2 += (double)diff * (double)diff;
    }
    int w = t >> 5, lane = t & 31;
#pragma unroll
    for (int o = 16; o > 0; o >>= 1) s2 += __shfl_down_sync(0xffffffffu, s2, o);
    if (lane == 0) sdk[w] = s2;
    __syncthreads();
    if (t == 0) {
        double v = 0.0;
#pragma unroll
        for (int i = 0; i < 8; i++) v += sdk[i];
        atomicAdd(&g_acc[0], v);
    }
}

// ---------- scalars ----------
__global__ void k_scalar(float* __restrict__ out, int out_size)
{
    double m   = g_acc[0] / ((double)B_ROWS * (double)COMM);
    double kld = -0.5 * g_acc[1] / (double)B_ROWS;
    double total = kld + 1.25 * m;
    out[out_size - 2] = (float)total;
    out[out_size - 1] = (float)kld;
}

extern "C" void kernel_launch(void* const* d_in, const int* in_sizes, int n_in,
                              void* d_out, int out_size)
{
    const float* x      = (const float*)d_in[0];
    const float* eps    = (const float*)d_in[1];
    const float* W_feat = (const float*)d_in[2];
    const float* b_feat = (const float*)d_in[3];
    const float* W0     = (const float*)d_in[4];
    const float* b0     = (const float*)d_in[5];
    const float* W1     = (const float*)d_in[6];
    const float* b1     = (const float*)d_in[7];
    const float* W_mu   = (const float*)d_in[8];
    const float* b_mu   = (const float*)d_in[9];
    const float* W_var  = (const float*)d_in[10];
    const float* b_var  = (const float*)d_in[11];
    const float* protos = (const float*)d_in[12];
    float* out = (float*)d_out;

    cudaFuncSetAttribute(k_dist_hmma, cudaFuncAttributeMaxDynamicSharedMemorySize, DSMEM);

    k_pn<<<KP / 8, 256>>>(protos);
    k_mlp<<<B_ROWS / 64, 256>>>(x, W_feat, b_feat, W0, b0, W1, b1);
    k_head<<<B_ROWS / 16, 256>>>(eps, W_mu, b_mu, W_var, b_var);
    k_dist_hmma<<<B_ROWS / 128, 512, DSMEM>>>();
    k_resolve<<<B_ROWS / 8, 256>>>(protos);
    k_final<<<B_ROWS / 32, 256>>>(protos, out);
    k_scalar<<<1, 1>>>(out, out_size);
}